// round 1
// baseline (speedup 1.0000x reference)
#include <cuda_runtime.h>
#include <math.h>

// Problem constants
#define BB   4
#define NQ   1024
#define NKV  2048
#define CC   1024
#define NH   16
#define DH   64
#define HID  4096

// Scratch (device globals: allocation-guard safe)
__device__ float g_xn [BB * NKV * CC];        // layernorm(x)
__device__ float g_qh [BB * NQ * CC];         // q @ Wq
__device__ float g_kv [BB * NKV * 2 * CC];    // xn @ Wkv
__device__ float g_y  [BB * NQ * CC];         // ctx gathered [B*n, C]
__device__ float g_q2 [BB * NQ * CC];         // q + proj
__device__ float g_t  [BB * NQ * CC];         // ln2(q2)
__device__ float g_hid[BB * NQ * HID];        // gelu(t@W1+b1)

// ---------------------------------------------------------------------------
// LayerNorm over last dim (ccols), one block per row
// ---------------------------------------------------------------------------
__global__ void ln_kernel(const float* __restrict__ x, const float* __restrict__ g,
                          const float* __restrict__ be, float* __restrict__ out, int ccols)
{
    int row = blockIdx.x;
    const float* p = x + (size_t)row * ccols;
    float* o = out + (size_t)row * ccols;
    int t = threadIdx.x;

    float s = 0.f, s2 = 0.f;
    for (int i = t; i < ccols; i += blockDim.x) { float v = p[i]; s += v; s2 += v * v; }

    __shared__ float r1[8], r2[8];
    #pragma unroll
    for (int off = 16; off; off >>= 1) {
        s  += __shfl_xor_sync(~0u, s,  off);
        s2 += __shfl_xor_sync(~0u, s2, off);
    }
    if ((t & 31) == 0) { r1[t >> 5] = s; r2[t >> 5] = s2; }
    __syncthreads();
    float ts = 0.f, ts2 = 0.f;
    #pragma unroll
    for (int i = 0; i < 8; i++) { ts += r1[i]; ts2 += r2[i]; }
    float mean = ts / ccols;
    float var  = ts2 / ccols - mean * mean;
    float inv  = rsqrtf(var + 1e-5f);

    for (int i = t; i < ccols; i += blockDim.x)
        o[i] = (p[i] - mean) * inv * g[i] + be[i];
}

// ---------------------------------------------------------------------------
// Generic SGEMM C[M,N] = A[M,K] @ B[K,N] (+ epilogue), 128x128x8 tile, 8x8/thread
// MODE 0: C = acc
// MODE 2: C = acc + bias[n] + res[m,n]
// MODE 3: C = gelu(acc + bias[n])
// M, N must be multiples of 128; K multiple of 8. All pointers float4-aligned.
// ---------------------------------------------------------------------------
template <int MODE>
__global__ void gemm128(const float* __restrict__ A, int lda,
                        const float* __restrict__ B, int ldb,
                        float* __restrict__ Cc, int ldc, int K,
                        const float* __restrict__ bias,
                        const float* __restrict__ res, int ldres)
{
    constexpr int BM = 128, BN = 128, BK = 8;
    __shared__ float As[BK][BM];
    __shared__ float Bs[BK][BN];

    int tid = threadIdx.x;
    int tx = tid & 15, ty = tid >> 4;
    int bm = blockIdx.y * BM, bn = blockIdx.x * BN;

    int arow = tid >> 1, acol = (tid & 1) << 2;      // A: 128 rows x 8 k
    int brow = tid >> 5, bcol = (tid & 31) << 2;     // B: 8 k x 128 n

    const float* Ap = A + (size_t)(bm + arow) * lda + acol;
    const float* Bp = B + (size_t)brow * ldb + bn + bcol;

    float acc[8][8] = {};

    for (int k0 = 0; k0 < K; k0 += BK) {
        float4 av = *(const float4*)Ap;
        float4 bv = *(const float4*)Bp;
        As[acol + 0][arow] = av.x;
        As[acol + 1][arow] = av.y;
        As[acol + 2][arow] = av.z;
        As[acol + 3][arow] = av.w;
        *(float4*)&Bs[brow][bcol] = bv;
        __syncthreads();

        #pragma unroll
        for (int kk = 0; kk < BK; kk++) {
            float4 a0 = *(const float4*)&As[kk][ty * 8];
            float4 a1 = *(const float4*)&As[kk][ty * 8 + 4];
            float4 b0 = *(const float4*)&Bs[kk][tx * 8];
            float4 b1 = *(const float4*)&Bs[kk][tx * 8 + 4];
            float ar[8] = {a0.x, a0.y, a0.z, a0.w, a1.x, a1.y, a1.z, a1.w};
            float br[8] = {b0.x, b0.y, b0.z, b0.w, b1.x, b1.y, b1.z, b1.w};
            #pragma unroll
            for (int i = 0; i < 8; i++)
                #pragma unroll
                for (int j = 0; j < 8; j++)
                    acc[i][j] = fmaf(ar[i], br[j], acc[i][j]);
        }
        __syncthreads();
        Ap += BK;
        Bp += (size_t)BK * ldb;
    }

    #pragma unroll
    for (int i = 0; i < 8; i++) {
        int gm = bm + ty * 8 + i;
        float* crow = Cc + (size_t)gm * ldc + bn + tx * 8;
        const float* rrow = (MODE == 2) ? (res + (size_t)gm * ldres + bn + tx * 8) : nullptr;
        #pragma unroll
        for (int j = 0; j < 8; j++) {
            float v = acc[i][j];
            if (MODE >= 2) v += bias[bn + tx * 8 + j];
            if (MODE == 2) v += rrow[j];
            if (MODE == 3) v = 0.5f * v * (1.0f + erff(v * 0.70710678118654752f));
            crow[j] = v;
        }
    }
}

// ---------------------------------------------------------------------------
// scores[b,h] = (qh_bh [n,64]) @ (k_bh [N,64])^T * scale  -> attn buffer
// Both operands K-contiguous (gemm NT). 128x128 tile over (n, N), K=64.
// ---------------------------------------------------------------------------
__global__ void scores_kernel(const float* __restrict__ qh, const float* __restrict__ kv,
                              float* __restrict__ attn)
{
    constexpr int BM = 128, BN = 128, BK = 8;
    __shared__ float As[BK][BM];
    __shared__ float Bs[BK][BN];

    int z = blockIdx.z;
    int b = z >> 4, hd = z & 15;
    const float* A  = qh + (size_t)b * NQ * CC + hd * DH;           // lda = CC
    const float* Bt = kv + (size_t)b * NKV * 2 * CC + hd * DH;      // ldb = 2*CC
    float* Cc = attn + (size_t)z * NQ * NKV;                        // ldc = NKV

    int tid = threadIdx.x;
    int tx = tid & 15, ty = tid >> 4;
    int bm = blockIdx.y * BM, bn = blockIdx.x * BN;
    int arow = tid >> 1, acol = (tid & 1) << 2;

    const float* Ap = A  + (size_t)(bm + arow) * CC + acol;
    const float* Bp = Bt + (size_t)(bn + arow) * (2 * CC) + acol;

    float acc[8][8] = {};

    for (int k0 = 0; k0 < DH; k0 += BK) {
        float4 av = *(const float4*)Ap;
        float4 bv = *(const float4*)Bp;
        As[acol + 0][arow] = av.x; As[acol + 1][arow] = av.y;
        As[acol + 2][arow] = av.z; As[acol + 3][arow] = av.w;
        Bs[acol + 0][arow] = bv.x; Bs[acol + 1][arow] = bv.y;
        Bs[acol + 2][arow] = bv.z; Bs[acol + 3][arow] = bv.w;
        __syncthreads();

        #pragma unroll
        for (int kk = 0; kk < BK; kk++) {
            float4 a0 = *(const float4*)&As[kk][ty * 8];
            float4 a1 = *(const float4*)&As[kk][ty * 8 + 4];
            float4 b0 = *(const float4*)&Bs[kk][tx * 8];
            float4 b1 = *(const float4*)&Bs[kk][tx * 8 + 4];
            float ar[8] = {a0.x, a0.y, a0.z, a0.w, a1.x, a1.y, a1.z, a1.w};
            float br[8] = {b0.x, b0.y, b0.z, b0.w, b1.x, b1.y, b1.z, b1.w};
            #pragma unroll
            for (int i = 0; i < 8; i++)
                #pragma unroll
                for (int j = 0; j < 8; j++)
                    acc[i][j] = fmaf(ar[i], br[j], acc[i][j]);
        }
        __syncthreads();
        Ap += BK;
        Bp += BK;
    }

    const float scale = 0.125f;  // d^-0.5, d=64
    #pragma unroll
    for (int i = 0; i < 8; i++) {
        float* crow = Cc + (size_t)(bm + ty * 8 + i) * NKV + bn + tx * 8;
        #pragma unroll
        for (int j = 0; j < 8; j++) crow[j] = acc[i][j] * scale;
    }
}

// ---------------------------------------------------------------------------
// In-place row softmax over N=2048, one block (256 thr) per row
// ---------------------------------------------------------------------------
__global__ void softmax_kernel(float* __restrict__ attn)
{
    float* p = attn + (size_t)blockIdx.x * NKV;
    int t = threadIdx.x;
    float v[8];
    float m = -1e30f;
    #pragma unroll
    for (int i = 0; i < 8; i++) { v[i] = p[t + i * 256]; m = fmaxf(m, v[i]); }

    __shared__ float red[8];
    #pragma unroll
    for (int off = 16; off; off >>= 1) m = fmaxf(m, __shfl_xor_sync(~0u, m, off));
    if ((t & 31) == 0) red[t >> 5] = m;
    __syncthreads();
    float mm = red[0];
    #pragma unroll
    for (int i = 1; i < 8; i++) mm = fmaxf(mm, red[i]);
    __syncthreads();

    float s = 0.f;
    #pragma unroll
    for (int i = 0; i < 8; i++) { v[i] = __expf(v[i] - mm); s += v[i]; }
    #pragma unroll
    for (int off = 16; off; off >>= 1) s += __shfl_xor_sync(~0u, s, off);
    if ((t & 31) == 0) red[t >> 5] = s;
    __syncthreads();
    float ts = 0.f;
    #pragma unroll
    for (int i = 0; i < 8; i++) ts += red[i];
    float inv = 1.0f / ts;
    #pragma unroll
    for (int i = 0; i < 8; i++) p[t + i * 256] = v[i] * inv;
}

// ---------------------------------------------------------------------------
// ctx[b,h] = attn_bh [n,N] @ v_bh [N,64]  -> scatter into y [B*n, C] at col h*64
// Tile 128 x 64 x 16, 8x4 per thread
// ---------------------------------------------------------------------------
__global__ void ctx_kernel(const float* __restrict__ attn, const float* __restrict__ kv,
                           float* __restrict__ y)
{
    constexpr int BM = 128, BN = 64, BK = 16;
    __shared__ float As[BK][BM];
    __shared__ float Bs[BK][BN];

    int z = blockIdx.z;
    int b = z >> 4, hd = z & 15;
    const float* A  = attn + (size_t)z * NQ * NKV;                       // lda = NKV
    const float* Bm = kv + (size_t)b * NKV * 2 * CC + CC + hd * DH;      // ldb = 2*CC
    float* Cc = y + (size_t)b * NQ * CC + hd * DH;                       // ldc = CC

    int tid = threadIdx.x;
    int tx = tid & 15, ty = tid >> 4;
    int bm = blockIdx.y * BM;

    int arow = tid >> 2, acol = (tid & 3) << 2;   // A tile 128x16, 2 float4/thr
    int brow = tid >> 4, bcol = (tid & 15) << 2;  // B tile 16x64, 1 float4/thr

    float acc[8][4] = {};

    for (int k0 = 0; k0 < NKV; k0 += BK) {
        float4 a0 = *(const float4*)(A + (size_t)(bm + arow) * NKV + k0 + acol);
        float4 a1 = *(const float4*)(A + (size_t)(bm + arow + 64) * NKV + k0 + acol);
        float4 bv = *(const float4*)(Bm + (size_t)(k0 + brow) * (2 * CC) + bcol);
        As[acol + 0][arow] = a0.x; As[acol + 1][arow] = a0.y;
        As[acol + 2][arow] = a0.z; As[acol + 3][arow] = a0.w;
        As[acol + 0][arow + 64] = a1.x; As[acol + 1][arow + 64] = a1.y;
        As[acol + 2][arow + 64] = a1.z; As[acol + 3][arow + 64] = a1.w;
        *(float4*)&Bs[brow][bcol] = bv;
        __syncthreads();

        #pragma unroll
        for (int kk = 0; kk < BK; kk++) {
            float4 a0r = *(const float4*)&As[kk][ty * 8];
            float4 a1r = *(const float4*)&As[kk][ty * 8 + 4];
            float4 b0r = *(const float4*)&Bs[kk][tx * 4];
            float ar[8] = {a0r.x, a0r.y, a0r.z, a0r.w, a1r.x, a1r.y, a1r.z, a1r.w};
            float br[4] = {b0r.x, b0r.y, b0r.z, b0r.w};
            #pragma unroll
            for (int i = 0; i < 8; i++)
                #pragma unroll
                for (int j = 0; j < 4; j++)
                    acc[i][j] = fmaf(ar[i], br[j], acc[i][j]);
        }
        __syncthreads();
    }

    #pragma unroll
    for (int i = 0; i < 8; i++) {
        float* crow = Cc + (size_t)(bm + ty * 8 + i) * CC + tx * 4;
        #pragma unroll
        for (int j = 0; j < 4; j++) crow[j] = acc[i][j];
    }
}

// ---------------------------------------------------------------------------
extern "C" void kernel_launch(void* const* d_in, const int* in_sizes, int n_in,
                              void* d_out, int out_size)
{
    const float* q     = (const float*)d_in[0];
    const float* x     = (const float*)d_in[1];
    const float* Wq    = (const float*)d_in[2];
    const float* Wkv   = (const float*)d_in[3];
    const float* Wproj = (const float*)d_in[4];
    const float* bproj = (const float*)d_in[5];
    const float* W1    = (const float*)d_in[6];
    const float* b1    = (const float*)d_in[7];
    const float* W2    = (const float*)d_in[8];
    const float* b2    = (const float*)d_in[9];
    const float* g1    = (const float*)d_in[10];
    const float* be1   = (const float*)d_in[11];
    const float* g2    = (const float*)d_in[12];
    const float* be2   = (const float*)d_in[13];

    float* out_q    = (float*)d_out;
    float* out_attn = out_q + (size_t)BB * NQ * CC;

    float *xn, *qh, *kv, *y, *q2, *t, *hid;
    cudaGetSymbolAddress((void**)&xn,  g_xn);
    cudaGetSymbolAddress((void**)&qh,  g_qh);
    cudaGetSymbolAddress((void**)&kv,  g_kv);
    cudaGetSymbolAddress((void**)&y,   g_y);
    cudaGetSymbolAddress((void**)&q2,  g_q2);
    cudaGetSymbolAddress((void**)&t,   g_t);
    cudaGetSymbolAddress((void**)&hid, g_hid);

    // 1) xn = LN(x)
    ln_kernel<<<BB * NKV, 256>>>(x, g1, be1, xn, CC);
    // 2) qh = q @ Wq                 [4096,1024]
    gemm128<0><<<dim3(CC / 128, BB * NQ / 128), 256>>>(q, CC, Wq, CC, qh, CC, CC,
                                                       nullptr, nullptr, 0);
    // 3) kv = xn @ Wkv               [8192,2048]
    gemm128<0><<<dim3(2 * CC / 128, BB * NKV / 128), 256>>>(xn, CC, Wkv, 2 * CC, kv, 2 * CC, CC,
                                                            nullptr, nullptr, 0);
    // 4) scores -> attn region of d_out (scaled)
    scores_kernel<<<dim3(NKV / 128, NQ / 128, BB * NH), 256>>>(qh, kv, out_attn);
    // 5) softmax in place
    softmax_kernel<<<BB * NH * NQ, 256>>>(out_attn);
    // 6) ctx = attn @ v -> y [4096,1024]
    ctx_kernel<<<dim3(1, NQ / 128, BB * NH), 256>>>(out_attn, kv, y);
    // 7) q2 = q + y @ Wproj + bproj
    gemm128<2><<<dim3(CC / 128, BB * NQ / 128), 256>>>(y, CC, Wproj, CC, q2, CC, CC,
                                                       bproj, q, CC);
    // 8) t = LN(q2)
    ln_kernel<<<BB * NQ, 256>>>(q2, g2, be2, t, CC);
    // 9) hid = gelu(t @ W1 + b1)     [4096,4096]
    gemm128<3><<<dim3(HID / 128, BB * NQ / 128), 256>>>(t, CC, W1, HID, hid, HID, CC,
                                                        b1, nullptr, 0);
    // 10) q_out = q2 + hid @ W2 + b2 -> q region of d_out
    gemm128<2><<<dim3(CC / 128, BB * NQ / 128), 256>>>(hid, HID, W2, CC, out_q, CC, HID,
                                                       b2, q2, CC);
}

// round 3
// speedup vs baseline: 2.0674x; 2.0674x over previous
#include <cuda_runtime.h>
#include <cstdint>
#include <math.h>

#define BB   4
#define NQ   1024
#define NKV  2048
#define CC   1024
#define NH   16
#define DH   64
#define HID  4096

// ---------------- scratch (device globals; allocation-guard safe) -----------
__device__ float g_xn [BB * NKV * CC];
__device__ float g_qh [BB * NQ * CC];
__device__ float g_kv [BB * NKV * 2 * CC];
__device__ float g_y  [BB * NQ * CC];
__device__ float g_q2 [BB * NQ * CC];
__device__ float g_t  [BB * NQ * CC];
__device__ float g_hid[BB * NQ * HID];
__device__ float g_kT [BB * CC * NKV];    // per-batch transposed K heads: [b][h*64+dd][NKV]

// ---------------------------------------------------------------------------
__device__ __forceinline__ uint32_t cvt_tf32(float f) {
    uint32_t u;
    asm("cvt.rna.tf32.f32 %0, %1;" : "=r"(u) : "f"(f));
    return u;
}

__device__ __forceinline__ void mma_tf32(float* c, const uint32_t* a, const uint32_t* b) {
    asm volatile(
        "mma.sync.aligned.m16n8k8.row.col.f32.tf32.tf32.f32 "
        "{%0,%1,%2,%3}, {%4,%5,%6,%7}, {%8,%9}, {%0,%1,%2,%3};"
        : "+f"(c[0]), "+f"(c[1]), "+f"(c[2]), "+f"(c[3])
        : "r"(a[0]), "r"(a[1]), "r"(a[2]), "r"(a[3]), "r"(b[0]), "r"(b[1]));
}

// ---------------------------------------------------------------------------
// Tensor-core tf32 GEMM: C[128 x BN] tile of  A[M,K] @ B[K,N]
// A row-major (lda), B row-major N-contiguous (ldb).  BK=32, 256 threads.
// MODE 0: C=acc  1: C=acc*scale  2: C=acc+bias[n]+res  3: C=gelu(acc+bias[n])
// ---------------------------------------------------------------------------
template <int BN, int MODE>
__global__ __launch_bounds__(256) void mma_gemm(
    const float* __restrict__ A, int lda, long saB, long saH,
    const float* __restrict__ B, int ldb, long sbB, long sbH,
    float* __restrict__ C, int ldc, long scB, long scH,
    int K, const float* __restrict__ bias,
    const float* __restrict__ res, int ldres, float scale)
{
    constexpr int BK  = 32;
    constexpr int AP  = BK + 4;            // A smem row pitch (floats)
    constexpr int BP  = BN + 8;            // B smem row pitch (floats)
    constexpr int WC  = (BN == 128) ? 4 : 2;
    constexpr int WM  = (BN == 128) ? 64 : 32;   // warp tile m
    constexpr int WN  = 32;                      // warp tile n
    constexpr int MT  = WM / 16;
    constexpr int NT  = WN / 8;
    constexpr int NB4 = BN / 32;           // float4 B loads per thread

    extern __shared__ __align__(16) uint32_t smem[];
    uint32_t* As[2] = { smem, smem + 128 * AP };
    uint32_t* Bs[2] = { smem + 2 * 128 * AP, smem + 2 * 128 * AP + BK * BP };

    const int tid  = threadIdx.x;
    const int wid  = tid >> 5;
    const int lane = tid & 31;
    const int wm   = (wid / WC) * WM;
    const int wn   = (wid % WC) * WN;

    const int z = blockIdx.z, zb = z >> 4, zh = z & 15;
    const int bm = blockIdx.y * 128, bn = blockIdx.x * BN;

    const float* Ab = A + (long)zb * saB + (long)zh * saH + (size_t)bm * lda;
    const float* Bb = B + (long)zb * sbB + (long)zh * sbH + bn;
    float*       Cb = C + (long)zb * scB + (long)zh * scH + (size_t)bm * ldc + bn;
    const float* Rb = (MODE == 2) ? res + (size_t)bm * ldres + bn : nullptr;

    // staging thread mapping
    const int ar  = tid >> 1;              // A row 0..127
    const int ac  = (tid & 1) * 16;        // A col base (floats)
    const int bkr = tid >> 3;              // B k-row 0..31
    const int bc  = (tid & 7) * 4;         // B col base (floats)

    const int nchunk = K >> 5;
    float4 av[4], bv[NB4];

    // prologue: load chunk 0
    {
        const float* Ak = Ab + ac;
        #pragma unroll
        for (int j = 0; j < 4; j++)
            av[j] = *(const float4*)(Ak + (size_t)ar * lda + 4 * j);
        const float* Bk = Bb + (size_t)bkr * ldb + bc;
        #pragma unroll
        for (int j = 0; j < NB4; j++)
            bv[j] = *(const float4*)(Bk + 32 * j);
    }
    // store chunk 0 (with tf32 rounding)
    {
        uint32_t* dA = As[0] + ar * AP + ac;
        #pragma unroll
        for (int j = 0; j < 4; j++) {
            uint4 u = { cvt_tf32(av[j].x), cvt_tf32(av[j].y), cvt_tf32(av[j].z), cvt_tf32(av[j].w) };
            *(uint4*)(dA + 4 * j) = u;
        }
        uint32_t* dB = Bs[0] + bkr * BP + bc;
        #pragma unroll
        for (int j = 0; j < NB4; j++) {
            uint4 u = { cvt_tf32(bv[j].x), cvt_tf32(bv[j].y), cvt_tf32(bv[j].z), cvt_tf32(bv[j].w) };
            *(uint4*)(dB + 32 * j) = u;
        }
    }
    __syncthreads();

    float acc[MT][NT][4];
    #pragma unroll
    for (int i = 0; i < MT; i++)
        #pragma unroll
        for (int j = 0; j < NT; j++)
            #pragma unroll
            for (int v = 0; v < 4; v++) acc[i][j][v] = 0.f;

    const int fr = lane >> 2, fc = lane & 3;

    int p = 0;
    for (int ci = 0; ci < nchunk; ci++) {
        if (ci + 1 < nchunk) {
            const float* Ak = Ab + (ci + 1) * BK + ac;
            #pragma unroll
            for (int j = 0; j < 4; j++)
                av[j] = *(const float4*)(Ak + (size_t)ar * lda + 4 * j);
            const float* Bk = Bb + (size_t)((ci + 1) * BK + bkr) * ldb + bc;
            #pragma unroll
            for (int j = 0; j < NB4; j++)
                bv[j] = *(const float4*)(Bk + 32 * j);
        }

        const uint32_t* sA = As[p];
        const uint32_t* sB = Bs[p];
        #pragma unroll
        for (int kk = 0; kk < 4; kk++) {
            const int k8 = kk * 8;
            uint32_t af[MT][4], bf[NT][2];
            #pragma unroll
            for (int i = 0; i < MT; i++) {
                const uint32_t* a0 = sA + (wm + 16 * i + fr) * AP + k8 + fc;
                af[i][0] = a0[0];
                af[i][1] = a0[8 * AP];
                af[i][2] = a0[4];
                af[i][3] = a0[8 * AP + 4];
            }
            #pragma unroll
            for (int j = 0; j < NT; j++) {
                const uint32_t* b0 = sB + (k8 + fc) * BP + wn + 8 * j + fr;
                bf[j][0] = b0[0];
                bf[j][1] = b0[4 * BP];
            }
            #pragma unroll
            for (int i = 0; i < MT; i++)
                #pragma unroll
                for (int j = 0; j < NT; j++)
                    mma_tf32(acc[i][j], af[i], bf[j]);
        }

        if (ci + 1 < nchunk) {
            uint32_t* dA = As[p ^ 1] + ar * AP + ac;
            #pragma unroll
            for (int j = 0; j < 4; j++) {
                uint4 u = { cvt_tf32(av[j].x), cvt_tf32(av[j].y), cvt_tf32(av[j].z), cvt_tf32(av[j].w) };
                *(uint4*)(dA + 4 * j) = u;
            }
            uint32_t* dB = Bs[p ^ 1] + bkr * BP + bc;
            #pragma unroll
            for (int j = 0; j < NB4; j++) {
                uint4 u = { cvt_tf32(bv[j].x), cvt_tf32(bv[j].y), cvt_tf32(bv[j].z), cvt_tf32(bv[j].w) };
                *(uint4*)(dB + 32 * j) = u;
            }
        }
        __syncthreads();
        p ^= 1;
    }

    // epilogue
    const int er = lane >> 2, ec = (lane & 3) * 2;
    #pragma unroll
    for (int i = 0; i < MT; i++) {
        #pragma unroll
        for (int rr = 0; rr < 2; rr++) {
            const int row = wm + 16 * i + er + 8 * rr;
            float* Crow = Cb + (size_t)row * ldc;
            const float* Rrow = (MODE == 2) ? Rb + (size_t)row * ldres : nullptr;
            #pragma unroll
            for (int j = 0; j < NT; j++) {
                const int col = wn + 8 * j + ec;
                float v0 = acc[i][j][2 * rr + 0];
                float v1 = acc[i][j][2 * rr + 1];
                if (MODE == 1) { v0 *= scale; v1 *= scale; }
                if (MODE == 2) {
                    v0 += bias[bn + col]     + Rrow[col];
                    v1 += bias[bn + col + 1] + Rrow[col + 1];
                }
                if (MODE == 3) {
                    v0 += bias[bn + col];
                    v1 += bias[bn + col + 1];
                    v0 = 0.5f * v0 * (1.0f + erff(v0 * 0.70710678118654752f));
                    v1 = 0.5f * v1 * (1.0f + erff(v1 * 0.70710678118654752f));
                }
                *(float2*)&Crow[col] = make_float2(v0, v1);
            }
        }
    }
}

// ---------------------------------------------------------------------------
// transpose: out[c][r] = in[r][c]; grid (Cn/32, R/32, Z); block (32,8)
// ---------------------------------------------------------------------------
__global__ void transpose_kernel(const float* __restrict__ in, int ld_in, long sb_in,
                                 float* __restrict__ out, int ld_out, long sb_out)
{
    __shared__ float tile[32][33];
    const float* ip = in + (long)blockIdx.z * sb_in;
    float* op = out + (long)blockIdx.z * sb_out;
    int r0 = blockIdx.y * 32, c0 = blockIdx.x * 32;
    int x = threadIdx.x, y = threadIdx.y;
    #pragma unroll
    for (int j = 0; j < 32; j += 8)
        tile[y + j][x] = ip[(size_t)(r0 + y + j) * ld_in + c0 + x];
    __syncthreads();
    #pragma unroll
    for (int j = 0; j < 32; j += 8)
        op[(size_t)(c0 + y + j) * ld_out + r0 + x] = tile[x][y + j];
}

// ---------------------------------------------------------------------------
// LayerNorm over last dim, one block per row
// ---------------------------------------------------------------------------
__global__ void ln_kernel(const float* __restrict__ x, const float* __restrict__ g,
                          const float* __restrict__ be, float* __restrict__ out, int ccols)
{
    int row = blockIdx.x;
    const float* p = x + (size_t)row * ccols;
    float* o = out + (size_t)row * ccols;
    int t = threadIdx.x;

    float s = 0.f, s2 = 0.f;
    for (int i = t; i < ccols; i += blockDim.x) { float v = p[i]; s += v; s2 += v * v; }
    __shared__ float r1[8], r2[8];
    #pragma unroll
    for (int off = 16; off; off >>= 1) {
        s  += __shfl_xor_sync(~0u, s,  off);
        s2 += __shfl_xor_sync(~0u, s2, off);
    }
    if ((t & 31) == 0) { r1[t >> 5] = s; r2[t >> 5] = s2; }
    __syncthreads();
    float ts = 0.f, ts2 = 0.f;
    #pragma unroll
    for (int i = 0; i < 8; i++) { ts += r1[i]; ts2 += r2[i]; }
    float mean = ts / ccols;
    float var  = ts2 / ccols - mean * mean;
    float inv  = rsqrtf(var + 1e-5f);
    for (int i = t; i < ccols; i += blockDim.x)
        o[i] = (p[i] - mean) * inv * g[i] + be[i];
}

// ---------------------------------------------------------------------------
// In-place row softmax over N=2048, one block (256 thr) per row
// ---------------------------------------------------------------------------
__global__ void softmax_kernel(float* __restrict__ attn)
{
    float* p = attn + (size_t)blockIdx.x * NKV;
    int t = threadIdx.x;
    float v[8];
    float m = -1e30f;
    #pragma unroll
    for (int i = 0; i < 8; i++) { v[i] = p[t + i * 256]; m = fmaxf(m, v[i]); }
    __shared__ float red[8];
    #pragma unroll
    for (int off = 16; off; off >>= 1) m = fmaxf(m, __shfl_xor_sync(~0u, m, off));
    if ((t & 31) == 0) red[t >> 5] = m;
    __syncthreads();
    float mm = red[0];
    #pragma unroll
    for (int i = 1; i < 8; i++) mm = fmaxf(mm, red[i]);
    __syncthreads();
    float s = 0.f;
    #pragma unroll
    for (int i = 0; i < 8; i++) { v[i] = __expf(v[i] - mm); s += v[i]; }
    #pragma unroll
    for (int off = 16; off; off >>= 1) s += __shfl_xor_sync(~0u, s, off);
    if ((t & 31) == 0) red[t >> 5] = s;
    __syncthreads();
    float ts = 0.f;
    #pragma unroll
    for (int i = 0; i < 8; i++) ts += red[i];
    float inv = 1.0f / ts;
    #pragma unroll
    for (int i = 0; i < 8; i++) p[t + i * 256] = v[i] * inv;
}

// ---------------------------------------------------------------------------
extern "C" void kernel_launch(void* const* d_in, const int* in_sizes, int n_in,
                              void* d_out, int out_size)
{
    const float* q     = (const float*)d_in[0];
    const float* x     = (const float*)d_in[1];
    const float* Wq    = (const float*)d_in[2];
    const float* Wkv   = (const float*)d_in[3];
    const float* Wproj = (const float*)d_in[4];
    const float* bproj = (const float*)d_in[5];
    const float* W1    = (const float*)d_in[6];
    const float* b1    = (const float*)d_in[7];
    const float* W2    = (const float*)d_in[8];
    const float* b2    = (const float*)d_in[9];
    const float* g1    = (const float*)d_in[10];
    const float* be1   = (const float*)d_in[11];
    const float* g2    = (const float*)d_in[12];
    const float* be2   = (const float*)d_in[13];

    float* out_q    = (float*)d_out;
    float* out_attn = out_q + (size_t)BB * NQ * CC;

    float *xn, *qh, *kv, *y, *q2, *t, *hid, *kT;
    cudaGetSymbolAddress((void**)&xn,  g_xn);
    cudaGetSymbolAddress((void**)&qh,  g_qh);
    cudaGetSymbolAddress((void**)&kv,  g_kv);
    cudaGetSymbolAddress((void**)&y,   g_y);
    cudaGetSymbolAddress((void**)&q2,  g_q2);
    cudaGetSymbolAddress((void**)&t,   g_t);
    cudaGetSymbolAddress((void**)&hid, g_hid);
    cudaGetSymbolAddress((void**)&kT,  g_kT);

    // dynamic smem: double-buffered A[128][36] + B[32][BN+8] in uint32
    const int SM128 = (2 * 128 * 36 + 2 * 32 * 136) * 4;   // 71680
    const int SM64  = (2 * 128 * 36 + 2 * 32 * 72) * 4;    // 55296
    cudaFuncSetAttribute(mma_gemm<128, 0>, cudaFuncAttributeMaxDynamicSharedMemorySize, SM128);
    cudaFuncSetAttribute(mma_gemm<128, 1>, cudaFuncAttributeMaxDynamicSharedMemorySize, SM128);
    cudaFuncSetAttribute(mma_gemm<128, 2>, cudaFuncAttributeMaxDynamicSharedMemorySize, SM128);
    cudaFuncSetAttribute(mma_gemm<128, 3>, cudaFuncAttributeMaxDynamicSharedMemorySize, SM128);
    cudaFuncSetAttribute(mma_gemm<64,  0>, cudaFuncAttributeMaxDynamicSharedMemorySize, SM64);

    dim3 tb(32, 8);

    // 1) xn = LN(x)
    ln_kernel<<<BB * NKV, 256>>>(x, g1, be1, xn, CC);

    // 2) qh = q @ Wq        M=4096, N=1024, K=1024   (Wq is [K,N] row-major already)
    mma_gemm<128, 0><<<dim3(CC / 128, BB * NQ / 128, 1), 256, SM128>>>(
        q, CC, 0, 0, Wq, CC, 0, 0, qh, CC, 0, 0, CC, nullptr, nullptr, 0, 0.f);

    // 3) kv = xn @ Wkv      M=8192, N=2048, K=1024
    mma_gemm<128, 0><<<dim3(2 * CC / 128, BB * NKV / 128, 1), 256, SM128>>>(
        xn, CC, 0, 0, Wkv, 2 * CC, 0, 0, kv, 2 * CC, 0, 0, CC, nullptr, nullptr, 0, 0.f);

    // 4) kT[b][h*64+dd][NKV] = transpose of k-half of kv
    transpose_kernel<<<dim3(CC / 32, NKV / 32, BB), tb>>>(
        kv, 2 * CC, (long)NKV * 2 * CC, kT, NKV, (long)CC * NKV);

    // 5) scores -> out_attn (scaled)   per (b,h): [1024,64] @ kT[64,2048]
    mma_gemm<128, 1><<<dim3(NKV / 128, NQ / 128, BB * NH), 256, SM128>>>(
        qh, CC, (long)NQ * CC, DH,
        kT, NKV, (long)CC * NKV, (long)DH * NKV,
        out_attn, NKV, (long)NH * NQ * NKV, (long)NQ * NKV,
        DH, nullptr, nullptr, 0, 0.125f);

    // 6) softmax in place
    softmax_kernel<<<BB * NH * NQ, 256>>>(out_attn);

    // 7) ctx = attn @ V -> y    per (b,h): [1024,2048] @ V[2048,64] (V half of kv, direct)
    mma_gemm<64, 0><<<dim3(1, NQ / 128, BB * NH), 256, SM64>>>(
        out_attn, NKV, (long)NH * NQ * NKV, (long)NQ * NKV,
        kv + CC, 2 * CC, (long)NKV * 2 * CC, DH,
        y, CC, (long)NQ * CC, DH,
        NKV, nullptr, nullptr, 0, 0.f);

    // 8) q2 = q + y @ Wproj + bproj
    mma_gemm<128, 2><<<dim3(CC / 128, BB * NQ / 128, 1), 256, SM128>>>(
        y, CC, 0, 0, Wproj, CC, 0, 0, q2, CC, 0, 0, CC, bproj, q, CC, 0.f);

    // 9) t = LN(q2)
    ln_kernel<<<BB * NQ, 256>>>(q2, g2, be2, t, CC);

    // 10) hid = gelu(t @ W1 + b1)    M=4096, N=4096, K=1024
    mma_gemm<128, 3><<<dim3(HID / 128, BB * NQ / 128, 1), 256, SM128>>>(
        t, CC, 0, 0, W1, HID, 0, 0, hid, HID, 0, 0, CC, b1, nullptr, 0, 0.f);

    // 11) q_out = q2 + hid @ W2 + b2    K=4096
    mma_gemm<128, 2><<<dim3(CC / 128, BB * NQ / 128, 1), 256, SM128>>>(
        hid, HID, 0, 0, W2, CC, 0, 0, out_q, CC, 0, 0, HID, b2, q2, CC, 0.f);
}

// round 5
// speedup vs baseline: 3.4219x; 1.6552x over previous
#include <cuda_runtime.h>
#include <cuda_fp16.h>
#include <cstdint>
#include <math.h>

#define BB   4
#define NQ   1024
#define NKV  2048
#define CC   1024
#define NH   16
#define DH   64
#define HID  4096

// ---------------- scratch (device globals; allocation-guard safe) -----------
__device__ float g_xn [BB * NKV * CC];
__device__ float g_qh [BB * NQ * CC];
__device__ float g_kv [BB * NKV * 2 * CC];
__device__ float g_y  [BB * NQ * CC];
__device__ float g_q2 [BB * NQ * CC];
__device__ float g_t  [BB * NQ * CC];
__device__ float g_hid[BB * NQ * HID];
__device__ float g_kT [BB * CC * NKV];    // [b][h*64+dd][NKV]

// ---------------------------------------------------------------------------
__device__ __forceinline__ uint32_t smem_u32(const void* p) {
    uint32_t a;
    asm("{ .reg .u64 t; cvta.to.shared.u64 t, %1; cvt.u32.u64 %0, t; }" : "=r"(a) : "l"(p));
    return a;
}
__device__ __forceinline__ uint32_t packh2(float x, float y) {
    uint32_t u;
    asm("cvt.rn.f16x2.f32 %0, %1, %2;" : "=r"(u) : "f"(y), "f"(x));
    return u;
}
__device__ __forceinline__ void mma_f16(float* c, const uint32_t* a, const uint32_t* b) {
    asm volatile(
        "mma.sync.aligned.m16n8k16.row.col.f32.f16.f16.f32 "
        "{%0,%1,%2,%3}, {%4,%5,%6,%7}, {%8,%9}, {%0,%1,%2,%3};"
        : "+f"(c[0]), "+f"(c[1]), "+f"(c[2]), "+f"(c[3])
        : "r"(a[0]), "r"(a[1]), "r"(a[2]), "r"(a[3]), "r"(b[0]), "r"(b[1]));
}
#define LDSM_X4(r0, r1, r2, r3, addr) \
    asm volatile("ldmatrix.sync.aligned.m8n8.x4.shared.b16 {%0,%1,%2,%3}, [%4];" \
                 : "=r"(r0), "=r"(r1), "=r"(r2), "=r"(r3) : "r"(addr))
#define LDSM_X4T(r0, r1, r2, r3, addr) \
    asm volatile("ldmatrix.sync.aligned.m8n8.x4.trans.shared.b16 {%0,%1,%2,%3}, [%4];" \
                 : "=r"(r0), "=r"(r1), "=r"(r2), "=r"(r3) : "r"(addr))

// ---------------------------------------------------------------------------
// fp16 tensor-core GEMM: C[128 x BN] tile of A[M,K] @ B[K,N], f32 accumulate.
// A row-major (lda), B row-major N-contiguous (ldb). BK=32, 256 threads.
// MODE 0: C=acc  1: C=acc*scale  2: C=acc+bias[n]+res  3: C=gelu(acc+bias[n])
// ---------------------------------------------------------------------------
template <int BN, int MODE>
__global__ __launch_bounds__(256) void mma_gemm(
    const float* __restrict__ A, int lda, long saB, long saH,
    const float* __restrict__ B, int ldb, long sbB, long sbH,
    float* __restrict__ C, int ldc, long scB, long scH,
    int K, const float* __restrict__ bias,
    const float* __restrict__ res, int ldres, float scale)
{
    constexpr int BK  = 32;
    constexpr int APH = BK + 8;            // A smem row pitch (halves) = 40 -> 80B
    constexpr int BPH = BN + 8;            // B smem row pitch (halves)
    constexpr int WC  = (BN == 128) ? 4 : 2;
    constexpr int WM  = (BN == 128) ? 64 : 32;
    constexpr int MT  = WM / 16;
    constexpr int NT  = 4;                 // WN=32 -> 4 n8 tiles
    constexpr int NB4 = BN / 32;
    constexpr int ABUF = 128 * APH * 2;    // bytes per A buffer
    constexpr int BBUF = BK * BPH * 2;     // bytes per B buffer

    extern __shared__ __align__(16) char smem[];
    __half* sAh[2] = { (__half*)smem, (__half*)(smem + ABUF) };
    __half* sBh[2] = { (__half*)(smem + 2 * ABUF), (__half*)(smem + 2 * ABUF + BBUF) };
    const uint32_t sA32[2] = { smem_u32(sAh[0]), smem_u32(sAh[1]) };
    const uint32_t sB32[2] = { smem_u32(sBh[0]), smem_u32(sBh[1]) };

    const int tid  = threadIdx.x;
    const int wid  = tid >> 5;
    const int lane = tid & 31;
    const int wm   = (wid / WC) * WM;
    const int wn   = (wid % WC) * 32;

    const int z = blockIdx.z, zb = z >> 4, zh = z & 15;
    const int bm = blockIdx.y * 128, bn = blockIdx.x * BN;

    const float* Ab = A + (long)zb * saB + (long)zh * saH + (size_t)bm * lda;
    const float* Bb = B + (long)zb * sbB + (long)zh * sbH + bn;
    float*       Cb = C + (long)zb * scB + (long)zh * scH + (size_t)bm * ldc + bn;
    const float* Rb = (MODE == 2) ? res + (size_t)bm * ldres + bn : nullptr;

    // staging thread mapping
    const int ar  = tid >> 1;              // A row 0..127
    const int ac  = (tid & 1) * 16;        // A col base (elements)
    const int bkr = tid >> 3;              // B k-row 0..31
    const int bc  = (tid & 7) * 4;         // B col base

    // ldmatrix lane addressing
    const int lr = ((lane >> 3) & 1) * 8 + (lane & 7);   // row within 16-group
    const int lc = ((lane >> 4) & 1) * 8;                // col group (halves)

    const int nchunk = K >> 5;
    float4 av[4], bv[NB4];

    // prologue: load + store chunk 0
    {
        const float* Ak = Ab + ac;
        #pragma unroll
        for (int j = 0; j < 4; j++)
            av[j] = *(const float4*)(Ak + (size_t)ar * lda + 4 * j);
        const float* Bk = Bb + (size_t)bkr * ldb + bc;
        #pragma unroll
        for (int j = 0; j < NB4; j++)
            bv[j] = *(const float4*)(Bk + 32 * j);

        uint32_t* dA = (uint32_t*)(sAh[0] + ar * APH + ac);
        uint4 u0 = { packh2(av[0].x, av[0].y), packh2(av[0].z, av[0].w),
                     packh2(av[1].x, av[1].y), packh2(av[1].z, av[1].w) };
        uint4 u1 = { packh2(av[2].x, av[2].y), packh2(av[2].z, av[2].w),
                     packh2(av[3].x, av[3].y), packh2(av[3].z, av[3].w) };
        *(uint4*)(dA + 0) = u0;
        *(uint4*)(dA + 4) = u1;
        #pragma unroll
        for (int j = 0; j < NB4; j++) {
            uint2 u = { packh2(bv[j].x, bv[j].y), packh2(bv[j].z, bv[j].w) };
            *(uint2*)(sBh[0] + bkr * BPH + bc + 32 * j) = u;
        }
    }
    __syncthreads();

    float acc[MT][NT][4];
    #pragma unroll
    for (int i = 0; i < MT; i++)
        #pragma unroll
        for (int j = 0; j < NT; j++)
            #pragma unroll
            for (int v = 0; v < 4; v++) acc[i][j][v] = 0.f;

    int p = 0;
    for (int ci = 0; ci < nchunk; ci++) {
        if (ci + 1 < nchunk) {
            const float* Ak = Ab + (ci + 1) * BK + ac;
            #pragma unroll
            for (int j = 0; j < 4; j++)
                av[j] = *(const float4*)(Ak + (size_t)ar * lda + 4 * j);
            const float* Bk = Bb + (size_t)((ci + 1) * BK + bkr) * ldb + bc;
            #pragma unroll
            for (int j = 0; j < NB4; j++)
                bv[j] = *(const float4*)(Bk + 32 * j);
        }

        // compute on buffer p: two k16 steps
        #pragma unroll
        for (int kk = 0; kk < 2; kk++) {
            uint32_t af[MT][4], bf[2][4];
            #pragma unroll
            for (int i = 0; i < MT; i++) {
                uint32_t addr = sA32[p] +
                    (uint32_t)(((wm + 16 * i + lr) * APH + kk * 16 + lc) * 2);
                LDSM_X4(af[i][0], af[i][1], af[i][2], af[i][3], addr);
            }
            #pragma unroll
            for (int jj = 0; jj < 2; jj++) {
                uint32_t addr = sB32[p] +
                    (uint32_t)(((kk * 16 + lr) * BPH + wn + 16 * jj + lc) * 2);
                LDSM_X4T(bf[jj][0], bf[jj][1], bf[jj][2], bf[jj][3], addr);
            }
            #pragma unroll
            for (int i = 0; i < MT; i++) {
                #pragma unroll
                for (int jj = 0; jj < 2; jj++) {
                    mma_f16(acc[i][2 * jj + 0], af[i], &bf[jj][0]);
                    mma_f16(acc[i][2 * jj + 1], af[i], &bf[jj][2]);
                }
            }
        }

        if (ci + 1 < nchunk) {
            uint32_t* dA = (uint32_t*)(sAh[p ^ 1] + ar * APH + ac);
            uint4 u0 = { packh2(av[0].x, av[0].y), packh2(av[0].z, av[0].w),
                         packh2(av[1].x, av[1].y), packh2(av[1].z, av[1].w) };
            uint4 u1 = { packh2(av[2].x, av[2].y), packh2(av[2].z, av[2].w),
                         packh2(av[3].x, av[3].y), packh2(av[3].z, av[3].w) };
            *(uint4*)(dA + 0) = u0;
            *(uint4*)(dA + 4) = u1;
            #pragma unroll
            for (int j = 0; j < NB4; j++) {
                uint2 u = { packh2(bv[j].x, bv[j].y), packh2(bv[j].z, bv[j].w) };
                *(uint2*)(sBh[p ^ 1] + bkr * BPH + bc + 32 * j) = u;
            }
        }
        __syncthreads();
        p ^= 1;
    }

    // epilogue
    const int er = lane >> 2, ec = (lane & 3) * 2;
    #pragma unroll
    for (int i = 0; i < MT; i++) {
        #pragma unroll
        for (int rr = 0; rr < 2; rr++) {
            const int row = wm + 16 * i + er + 8 * rr;
            float* Crow = Cb + (size_t)row * ldc;
            const float* Rrow = (MODE == 2) ? Rb + (size_t)row * ldres : nullptr;
            #pragma unroll
            for (int j = 0; j < NT; j++) {
                const int col = wn + 8 * j + ec;
                float v0 = acc[i][j][2 * rr + 0];
                float v1 = acc[i][j][2 * rr + 1];
                if (MODE == 1) { v0 *= scale; v1 *= scale; }
                if (MODE == 2) {
                    v0 += bias[bn + col]     + Rrow[col];
                    v1 += bias[bn + col + 1] + Rrow[col + 1];
                }
                if (MODE == 3) {
                    v0 += bias[bn + col];
                    v1 += bias[bn + col + 1];
                    v0 = 0.5f * v0 * (1.0f + erff(v0 * 0.70710678118654752f));
                    v1 = 0.5f * v1 * (1.0f + erff(v1 * 0.70710678118654752f));
                }
                *(float2*)&Crow[col] = make_float2(v0, v1);
            }
        }
    }
}

// ---------------------------------------------------------------------------
__global__ void transpose_kernel(const float* __restrict__ in, int ld_in, long sb_in,
                                 float* __restrict__ out, int ld_out, long sb_out)
{
    __shared__ float tile[32][33];
    const float* ip = in + (long)blockIdx.z * sb_in;
    float* op = out + (long)blockIdx.z * sb_out;
    int r0 = blockIdx.y * 32, c0 = blockIdx.x * 32;
    int x = threadIdx.x, y = threadIdx.y;
    #pragma unroll
    for (int j = 0; j < 32; j += 8)
        tile[y + j][x] = ip[(size_t)(r0 + y + j) * ld_in + c0 + x];
    __syncthreads();
    #pragma unroll
    for (int j = 0; j < 32; j += 8)
        op[(size_t)(c0 + y + j) * ld_out + r0 + x] = tile[x][y + j];
}

// ---------------------------------------------------------------------------
__global__ void ln_kernel(const float* __restrict__ x, const float* __restrict__ g,
                          const float* __restrict__ be, float* __restrict__ out, int ccols)
{
    int row = blockIdx.x;
    const float* p = x + (size_t)row * ccols;
    float* o = out + (size_t)row * ccols;
    int t = threadIdx.x;

    float s = 0.f, s2 = 0.f;
    for (int i = t; i < ccols; i += blockDim.x) { float v = p[i]; s += v; s2 += v * v; }
    __shared__ float r1[8], r2[8];
    #pragma unroll
    for (int off = 16; off; off >>= 1) {
        s  += __shfl_xor_sync(~0u, s,  off);
        s2 += __shfl_xor_sync(~0u, s2, off);
    }
    if ((t & 31) == 0) { r1[t >> 5] = s; r2[t >> 5] = s2; }
    __syncthreads();
    float ts = 0.f, ts2 = 0.f;
    #pragma unroll
    for (int i = 0; i < 8; i++) { ts += r1[i]; ts2 += r2[i]; }
    float mean = ts / ccols;
    float var  = ts2 / ccols - mean * mean;
    float inv  = rsqrtf(var + 1e-5f);
    for (int i = t; i < ccols; i += blockDim.x)
        o[i] = (p[i] - mean) * inv * g[i] + be[i];
}

// ---------------------------------------------------------------------------
__global__ void softmax_kernel(float* __restrict__ attn)
{
    float* p = attn + (size_t)blockIdx.x * NKV;
    int t = threadIdx.x;
    float v[8];
    float m = -1e30f;
    #pragma unroll
    for (int i = 0; i < 8; i++) { v[i] = p[t + i * 256]; m = fmaxf(m, v[i]); }
    __shared__ float red[8];
    #pragma unroll
    for (int off = 16; off; off >>= 1) m = fmaxf(m, __shfl_xor_sync(~0u, m, off));
    if ((t & 31) == 0) red[t >> 5] = m;
    __syncthreads();
    float mm = red[0];
    #pragma unroll
    for (int i = 1; i < 8; i++) mm = fmaxf(mm, red[i]);
    __syncthreads();
    float s = 0.f;
    #pragma unroll
    for (int i = 0; i < 8; i++) { v[i] = __expf(v[i] - mm); s += v[i]; }
    #pragma unroll
    for (int off = 16; off; off >>= 1) s += __shfl_xor_sync(~0u, s, off);
    if ((t & 31) == 0) red[t >> 5] = s;
    __syncthreads();
    float ts = 0.f;
    #pragma unroll
    for (int i = 0; i < 8; i++) ts += red[i];
    float inv = 1.0f / ts;
    #pragma unroll
    for (int i = 0; i < 8; i++) p[t + i * 256] = v[i] * inv;
}

// ---------------------------------------------------------------------------
extern "C" void kernel_launch(void* const* d_in, const int* in_sizes, int n_in,
                              void* d_out, int out_size)
{
    const float* q     = (const float*)d_in[0];
    const float* x     = (const float*)d_in[1];
    const float* Wq    = (const float*)d_in[2];
    const float* Wkv   = (const float*)d_in[3];
    const float* Wproj = (const float*)d_in[4];
    const float* bproj = (const float*)d_in[5];
    const float* W1    = (const float*)d_in[6];
    const float* b1    = (const float*)d_in[7];
    const float* W2    = (const float*)d_in[8];
    const float* b2    = (const float*)d_in[9];
    const float* g1    = (const float*)d_in[10];
    const float* be1   = (const float*)d_in[11];
    const float* g2    = (const float*)d_in[12];
    const float* be2   = (const float*)d_in[13];

    float* out_q    = (float*)d_out;
    float* out_attn = out_q + (size_t)BB * NQ * CC;

    float *xn, *qh, *kv, *y, *q2, *t, *hid, *kT;
    cudaGetSymbolAddress((void**)&xn,  g_xn);
    cudaGetSymbolAddress((void**)&qh,  g_qh);
    cudaGetSymbolAddress((void**)&kv,  g_kv);
    cudaGetSymbolAddress((void**)&y,   g_y);
    cudaGetSymbolAddress((void**)&q2,  g_q2);
    cudaGetSymbolAddress((void**)&t,   g_t);
    cudaGetSymbolAddress((void**)&hid, g_hid);
    cudaGetSymbolAddress((void**)&kT,  g_kT);

    // dynamic smem: 2*A(128x40 half) + 2*B(32x(BN+8) half)
    const int SM128 = 2 * (128 * 40 * 2) + 2 * (32 * 136 * 2);   // 37888
    const int SM64  = 2 * (128 * 40 * 2) + 2 * (32 * 72 * 2);    // 29696
    cudaFuncSetAttribute(mma_gemm<128, 0>, cudaFuncAttributeMaxDynamicSharedMemorySize, SM128);
    cudaFuncSetAttribute(mma_gemm<128, 1>, cudaFuncAttributeMaxDynamicSharedMemorySize, SM128);
    cudaFuncSetAttribute(mma_gemm<128, 2>, cudaFuncAttributeMaxDynamicSharedMemorySize, SM128);
    cudaFuncSetAttribute(mma_gemm<128, 3>, cudaFuncAttributeMaxDynamicSharedMemorySize, SM128);
    cudaFuncSetAttribute(mma_gemm<64,  0>, cudaFuncAttributeMaxDynamicSharedMemorySize, SM64);

    dim3 tb(32, 8);

    // 1) xn = LN(x)
    ln_kernel<<<BB * NKV, 256>>>(x, g1, be1, xn, CC);

    // 2) qh = q @ Wq
    mma_gemm<128, 0><<<dim3(CC / 128, BB * NQ / 128, 1), 256, SM128>>>(
        q, CC, 0, 0, Wq, CC, 0, 0, qh, CC, 0, 0, CC, nullptr, nullptr, 0, 0.f);

    // 3) kv = xn @ Wkv
    mma_gemm<128, 0><<<dim3(2 * CC / 128, BB * NKV / 128, 1), 256, SM128>>>(
        xn, CC, 0, 0, Wkv, 2 * CC, 0, 0, kv, 2 * CC, 0, 0, CC, nullptr, nullptr, 0, 0.f);

    // 4) kT = transpose of k-half of kv
    transpose_kernel<<<dim3(CC / 32, NKV / 32, BB), tb>>>(
        kv, 2 * CC, (long)NKV * 2 * CC, kT, NKV, (long)CC * NKV);

    // 5) scores -> out_attn (scaled)
    mma_gemm<128, 1><<<dim3(NKV / 128, NQ / 128, BB * NH), 256, SM128>>>(
        qh, CC, (long)NQ * CC, DH,
        kT, NKV, (long)CC * NKV, (long)DH * NKV,
        out_attn, NKV, (long)NH * NQ * NKV, (long)NQ * NKV,
        DH, nullptr, nullptr, 0, 0.125f);

    // 6) softmax in place
    softmax_kernel<<<BB * NH * NQ, 256>>>(out_attn);

    // 7) ctx = attn @ V -> y
    mma_gemm<64, 0><<<dim3(1, NQ / 128, BB * NH), 256, SM64>>>(
        out_attn, NKV, (long)NH * NQ * NKV, (long)NQ * NKV,
        kv + CC, 2 * CC, (long)NKV * 2 * CC, DH,
        y, CC, (long)NQ * CC, DH,
        NKV, nullptr, nullptr, 0, 0.f);

    // 8) q2 = q + y @ Wproj + bproj
    mma_gemm<128, 2><<<dim3(CC / 128, BB * NQ / 128, 1), 256, SM128>>>(
        y, CC, 0, 0, Wproj, CC, 0, 0, q2, CC, 0, 0, CC, bproj, q, CC, 0.f);

    // 9) t = LN(q2)
    ln_kernel<<<BB * NQ, 256>>>(q2, g2, be2, t, CC);

    // 10) hid = gelu(t @ W1 + b1)
    mma_gemm<128, 3><<<dim3(HID / 128, BB * NQ / 128, 1), 256, SM128>>>(
        t, CC, 0, 0, W1, HID, 0, 0, hid, HID, 0, 0, CC, b1, nullptr, 0, 0.f);

    // 11) q_out = q2 + hid @ W2 + b2
    mma_gemm<128, 2><<<dim3(CC / 128, BB * NQ / 128, 1), 256, SM128>>>(
        hid, HID, 0, 0, W2, CC, 0, 0, out_q, CC, 0, 0, HID, b2, q2, CC, 0.f);
}

// round 6
// speedup vs baseline: 5.1913x; 1.5170x over previous
#include <cuda_runtime.h>
#include <cuda_fp16.h>
#include <cstdint>
#include <math.h>

#define BB   4
#define NQ   1024
#define NKV  2048
#define CC   1024
#define NH   16
#define DH   64
#define HID  4096

// ---------------- scratch (device globals; allocation-guard safe) -----------
__device__ __half g_q16 [BB * NQ * CC];
__device__ __half g_xn16[BB * NKV * CC];
__device__ __half g_qh16[BB * NQ * CC];
__device__ __half g_kv16[BB * NKV * 2 * CC];
__device__ __half g_kT16[BB * CC * NKV];
__device__ __half g_at16[(size_t)BB * NH * NQ * NKV];
__device__ __half g_y16 [BB * NQ * CC];
__device__ __half g_t16 [BB * NQ * CC];
__device__ __half g_hid16[BB * NQ * HID];
__device__ float  g_q2  [BB * NQ * CC];
__device__ __half g_wq16 [CC * CC];
__device__ __half g_wkv16[CC * 2 * CC];
__device__ __half g_wp16 [CC * CC];
__device__ __half g_w116 [CC * HID];
__device__ __half g_w216 [HID * CC];

// ---------------------------------------------------------------------------
__device__ __forceinline__ uint32_t smem_u32(const void* p) {
    uint32_t a;
    asm("{ .reg .u64 t; cvta.to.shared.u64 t, %1; cvt.u32.u64 %0, t; }" : "=r"(a) : "l"(p));
    return a;
}
__device__ __forceinline__ uint32_t packh2(float x, float y) {
    uint32_t u;
    asm("cvt.rn.f16x2.f32 %0, %1, %2;" : "=r"(u) : "f"(y), "f"(x));
    return u;
}
__device__ __forceinline__ void cpasync16(uint32_t dst, const void* src) {
    asm volatile("cp.async.ca.shared.global [%0], [%1], 16;" :: "r"(dst), "l"(src));
}
#define CP_COMMIT() asm volatile("cp.async.commit_group;" ::: "memory")
#define CP_WAIT(N)  asm volatile("cp.async.wait_group %0;" :: "n"(N) : "memory")

__device__ __forceinline__ void mma_f16(float* c, const uint32_t* a, const uint32_t* b) {
    asm volatile(
        "mma.sync.aligned.m16n8k16.row.col.f32.f16.f16.f32 "
        "{%0,%1,%2,%3}, {%4,%5,%6,%7}, {%8,%9}, {%0,%1,%2,%3};"
        : "+f"(c[0]), "+f"(c[1]), "+f"(c[2]), "+f"(c[3])
        : "r"(a[0]), "r"(a[1]), "r"(a[2]), "r"(a[3]), "r"(b[0]), "r"(b[1]));
}
#define LDSM_X4(r0, r1, r2, r3, addr) \
    asm volatile("ldmatrix.sync.aligned.m8n8.x4.shared.b16 {%0,%1,%2,%3}, [%4];" \
                 : "=r"(r0), "=r"(r1), "=r"(r2), "=r"(r3) : "r"(addr))
#define LDSM_X4T(r0, r1, r2, r3, addr) \
    asm volatile("ldmatrix.sync.aligned.m8n8.x4.trans.shared.b16 {%0,%1,%2,%3}, [%4];" \
                 : "=r"(r0), "=r"(r1), "=r"(r2), "=r"(r3) : "r"(addr))

// ---------------------------------------------------------------------------
// fp16 tensor-core GEMM, cp.async 3-stage pipeline.
// C[128 x BN] tile of A[M,K] @ B[K,N], f32 accumulate. A,B fp16 in GMEM.
// MODE 0: v=acc  1: v=acc*scale  2: v=acc+bias[n]+res  3: v=gelu(acc+bias[n])
// WF: write float C; WH: write half Ch (same strides).
// ---------------------------------------------------------------------------
template <int BN, int MODE, bool WF, bool WH>
__global__ __launch_bounds__(256) void mma_gemm_h(
    const __half* __restrict__ A, int lda, long saB, long saH,
    const __half* __restrict__ B, int ldb, long sbB, long sbH,
    float* __restrict__ Cf, __half* __restrict__ Ch, int ldc, long scB, long scH,
    int K, const float* __restrict__ bias,
    const float* __restrict__ res, int ldres, float scale)
{
    constexpr int S    = 3;
    constexpr int APH  = 40;               // A smem pitch (halves) -> 80 B
    constexpr int BPH  = BN + 8;           // B smem pitch (halves)
    constexpr int ABUF = 128 * APH * 2;
    constexpr int BBUF = 32 * BPH * 2;
    constexpr int STG  = ABUF + BBUF;
    constexpr int WC   = (BN == 128) ? 4 : 2;
    constexpr int WM   = (BN == 128) ? 64 : 32;
    constexpr int MT   = WM / 16;
    constexpr int NT   = 4;
    constexpr int BCH  = BN / 64;          // B chunks per thread (2 or 1)
    constexpr int BROWCH = BN / 8;         // 16B chunks per B row

    extern __shared__ __align__(16) char smem[];
    const uint32_t sb0 = smem_u32(smem);

    const int tid  = threadIdx.x;
    const int wid  = tid >> 5;
    const int lane = tid & 31;
    const int wm   = (wid / WC) * WM;
    const int wn   = (wid % WC) * 32;

    const int z = blockIdx.z, zb = z >> 4, zh = z & 15;
    const int bm = blockIdx.y * 128, bn = blockIdx.x * BN;

    const __half* Ab = A + (long)zb * saB + (long)zh * saH + (size_t)bm * lda;
    const __half* Bb = B + (long)zb * sbB + (long)zh * sbH + bn;
    float*  Cfb = WF ? Cf + (long)zb * scB + (long)zh * scH + (size_t)bm * ldc + bn : nullptr;
    __half* Chb = WH ? Ch + (long)zb * scB + (long)zh * scH + (size_t)bm * ldc + bn : nullptr;
    const float* Rb = (MODE == 2) ? res + (size_t)bm * ldres + bn : nullptr;

    const int nchunk = K >> 5;

    // ---- async stage issue ----
    auto issue = [&](int ci) {
        const int s = ci % S;
        const uint32_t sA = sb0 + s * STG;
        const uint32_t sB = sA + ABUF;
        const int k0 = ci * 32;
        #pragma unroll
        for (int u = 0; u < 2; u++) {
            int c = tid + u * 256;
            int row = c >> 2, col = c & 3;
            cpasync16(sA + row * 80 + col * 16,
                      Ab + (size_t)row * lda + k0 + col * 8);
        }
        #pragma unroll
        for (int u = 0; u < BCH; u++) {
            int c = tid + u * 256;
            int row = c / BROWCH, col = c % BROWCH;
            cpasync16(sB + row * (BPH * 2) + col * 16,
                      Bb + (size_t)(k0 + row) * ldb + col * 8);
        }
        CP_COMMIT();
    };

    #pragma unroll
    for (int s = 0; s < S - 1; s++)
        if (s < nchunk) issue(s);

    float acc[MT][NT][4];
    #pragma unroll
    for (int i = 0; i < MT; i++)
        #pragma unroll
        for (int j = 0; j < NT; j++)
            #pragma unroll
            for (int v = 0; v < 4; v++) acc[i][j][v] = 0.f;

    const int lr = ((lane >> 3) & 1) * 8 + (lane & 7);
    const int lc = ((lane >> 4) & 1) * 8;

    for (int ci = 0; ci < nchunk; ci++) {
        if (ci + 2 < nchunk) { CP_WAIT(1); } else { CP_WAIT(0); }
        __syncthreads();
        if (ci + 2 < nchunk) issue(ci + 2);

        const uint32_t sA = sb0 + (ci % S) * STG;
        const uint32_t sB = sA + ABUF;
        #pragma unroll
        for (int kk = 0; kk < 2; kk++) {
            uint32_t af[MT][4], bf[2][4];
            #pragma unroll
            for (int i = 0; i < MT; i++) {
                uint32_t addr = sA + (uint32_t)(((wm + 16 * i + lr) * APH + kk * 16 + lc) * 2);
                LDSM_X4(af[i][0], af[i][1], af[i][2], af[i][3], addr);
            }
            #pragma unroll
            for (int jj = 0; jj < 2; jj++) {
                uint32_t addr = sB + (uint32_t)(((kk * 16 + lr) * BPH + wn + 16 * jj + lc) * 2);
                LDSM_X4T(bf[jj][0], bf[jj][1], bf[jj][2], bf[jj][3], addr);
            }
            #pragma unroll
            for (int i = 0; i < MT; i++) {
                #pragma unroll
                for (int jj = 0; jj < 2; jj++) {
                    mma_f16(acc[i][2 * jj + 0], af[i], &bf[jj][0]);
                    mma_f16(acc[i][2 * jj + 1], af[i], &bf[jj][2]);
                }
            }
        }
        __syncthreads();
    }

    // epilogue
    const int er = lane >> 2, ec = (lane & 3) * 2;
    #pragma unroll
    for (int i = 0; i < MT; i++) {
        #pragma unroll
        for (int rr = 0; rr < 2; rr++) {
            const int row = wm + 16 * i + er + 8 * rr;
            float*  Cfrow = WF ? Cfb + (size_t)row * ldc : nullptr;
            __half* Chrow = WH ? Chb + (size_t)row * ldc : nullptr;
            const float* Rrow = (MODE == 2) ? Rb + (size_t)row * ldres : nullptr;
            #pragma unroll
            for (int j = 0; j < NT; j++) {
                const int col = wn + 8 * j + ec;
                float v0 = acc[i][j][2 * rr + 0];
                float v1 = acc[i][j][2 * rr + 1];
                if (MODE == 1) { v0 *= scale; v1 *= scale; }
                if (MODE == 2) {
                    v0 += bias[bn + col]     + Rrow[col];
                    v1 += bias[bn + col + 1] + Rrow[col + 1];
                }
                if (MODE == 3) {
                    v0 += bias[bn + col];
                    v1 += bias[bn + col + 1];
                    v0 = 0.5f * v0 * (1.0f + erff(v0 * 0.70710678118654752f));
                    v1 = 0.5f * v1 * (1.0f + erff(v1 * 0.70710678118654752f));
                }
                if (WF) *(float2*)&Cfrow[col] = make_float2(v0, v1);
                if (WH) *(uint32_t*)&Chrow[col] = packh2(v0, v1);
            }
        }
    }
}

// ---------------------------------------------------------------------------
__global__ void f2h_kernel(const float* __restrict__ in, __half* __restrict__ out, int n)
{
    int i = (blockIdx.x * blockDim.x + threadIdx.x) * 4;
    if (i < n) {
        float4 v = *(const float4*)(in + i);
        uint2 u = { packh2(v.x, v.y), packh2(v.z, v.w) };
        *(uint2*)(out + i) = u;
    }
}

// ---------------------------------------------------------------------------
__global__ void transpose_h(const __half* __restrict__ in, int ld_in, long sb_in,
                            __half* __restrict__ out, int ld_out, long sb_out)
{
    __shared__ __half tile[32][34];
    const __half* ip = in + (long)blockIdx.z * sb_in;
    __half* op = out + (long)blockIdx.z * sb_out;
    int r0 = blockIdx.y * 32, c0 = blockIdx.x * 32;
    int x = threadIdx.x, y = threadIdx.y;
    #pragma unroll
    for (int j = 0; j < 32; j += 8)
        tile[y + j][x] = ip[(size_t)(r0 + y + j) * ld_in + c0 + x];
    __syncthreads();
    #pragma unroll
    for (int j = 0; j < 32; j += 8)
        op[(size_t)(c0 + y + j) * ld_out + r0 + x] = tile[x][y + j];
}

// ---------------------------------------------------------------------------
// LayerNorm over last dim -> fp16 output
// ---------------------------------------------------------------------------
__global__ void ln_kernel_h(const float* __restrict__ x, const float* __restrict__ g,
                            const float* __restrict__ be, __half* __restrict__ out, int ccols)
{
    int row = blockIdx.x;
    const float* p = x + (size_t)row * ccols;
    __half* o = out + (size_t)row * ccols;
    int t = threadIdx.x;

    float s = 0.f, s2 = 0.f;
    for (int i = t; i < ccols; i += blockDim.x) { float v = p[i]; s += v; s2 += v * v; }
    __shared__ float r1[8], r2[8];
    #pragma unroll
    for (int off = 16; off; off >>= 1) {
        s  += __shfl_xor_sync(~0u, s,  off);
        s2 += __shfl_xor_sync(~0u, s2, off);
    }
    if ((t & 31) == 0) { r1[t >> 5] = s; r2[t >> 5] = s2; }
    __syncthreads();
    float ts = 0.f, ts2 = 0.f;
    #pragma unroll
    for (int i = 0; i < 8; i++) { ts += r1[i]; ts2 += r2[i]; }
    float mean = ts / ccols;
    float var  = ts2 / ccols - mean * mean;
    float inv  = rsqrtf(var + 1e-5f);
    for (int i = t; i < ccols; i += blockDim.x)
        o[i] = __float2half((p[i] - mean) * inv * g[i] + be[i]);
}

// ---------------------------------------------------------------------------
// row softmax over N=2048: fp32 in/out (output tensor) + fp16 copy
// ---------------------------------------------------------------------------
__global__ void softmax_kernel(float* __restrict__ attn, __half* __restrict__ attn16)
{
    float*  p  = attn   + (size_t)blockIdx.x * NKV;
    __half* ph = attn16 + (size_t)blockIdx.x * NKV;
    int t = threadIdx.x;
    float v[8];
    float m = -1e30f;
    #pragma unroll
    for (int i = 0; i < 8; i++) { v[i] = p[t + i * 256]; m = fmaxf(m, v[i]); }
    __shared__ float red[8];
    #pragma unroll
    for (int off = 16; off; off >>= 1) m = fmaxf(m, __shfl_xor_sync(~0u, m, off));
    if ((t & 31) == 0) red[t >> 5] = m;
    __syncthreads();
    float mm = red[0];
    #pragma unroll
    for (int i = 1; i < 8; i++) mm = fmaxf(mm, red[i]);
    __syncthreads();
    float s = 0.f;
    #pragma unroll
    for (int i = 0; i < 8; i++) { v[i] = __expf(v[i] - mm); s += v[i]; }
    #pragma unroll
    for (int off = 16; off; off >>= 1) s += __shfl_xor_sync(~0u, s, off);
    if ((t & 31) == 0) red[t >> 5] = s;
    __syncthreads();
    float ts = 0.f;
    #pragma unroll
    for (int i = 0; i < 8; i++) ts += red[i];
    float inv = 1.0f / ts;
    #pragma unroll
    for (int i = 0; i < 8; i++) {
        float o = v[i] * inv;
        p[t + i * 256]  = o;
        ph[t + i * 256] = __float2half(o);
    }
}

// ---------------------------------------------------------------------------
extern "C" void kernel_launch(void* const* d_in, const int* in_sizes, int n_in,
                              void* d_out, int out_size)
{
    const float* q     = (const float*)d_in[0];
    const float* x     = (const float*)d_in[1];
    const float* Wq    = (const float*)d_in[2];
    const float* Wkv   = (const float*)d_in[3];
    const float* Wproj = (const float*)d_in[4];
    const float* bproj = (const float*)d_in[5];
    const float* W1    = (const float*)d_in[6];
    const float* b1    = (const float*)d_in[7];
    const float* W2    = (const float*)d_in[8];
    const float* b2    = (const float*)d_in[9];
    const float* g1    = (const float*)d_in[10];
    const float* be1   = (const float*)d_in[11];
    const float* g2    = (const float*)d_in[12];
    const float* be2   = (const float*)d_in[13];

    float* out_q    = (float*)d_out;
    float* out_attn = out_q + (size_t)BB * NQ * CC;

    __half *q16, *xn16, *qh16, *kv16, *kT16, *at16, *y16, *t16, *hid16;
    __half *wq16, *wkv16, *wp16, *w116, *w216;
    float  *q2;
    cudaGetSymbolAddress((void**)&q16,  g_q16);
    cudaGetSymbolAddress((void**)&xn16, g_xn16);
    cudaGetSymbolAddress((void**)&qh16, g_qh16);
    cudaGetSymbolAddress((void**)&kv16, g_kv16);
    cudaGetSymbolAddress((void**)&kT16, g_kT16);
    cudaGetSymbolAddress((void**)&at16, g_at16);
    cudaGetSymbolAddress((void**)&y16,  g_y16);
    cudaGetSymbolAddress((void**)&t16,  g_t16);
    cudaGetSymbolAddress((void**)&hid16,g_hid16);
    cudaGetSymbolAddress((void**)&q2,   g_q2);
    cudaGetSymbolAddress((void**)&wq16, g_wq16);
    cudaGetSymbolAddress((void**)&wkv16,g_wkv16);
    cudaGetSymbolAddress((void**)&wp16, g_wp16);
    cudaGetSymbolAddress((void**)&w116, g_w116);
    cudaGetSymbolAddress((void**)&w216, g_w216);

    const int SM128 = 3 * (128 * 40 * 2 + 32 * 136 * 2);   // 56832
    const int SM64  = 3 * (128 * 40 * 2 + 32 * 72 * 2);    // 44544
    cudaFuncSetAttribute((const void*)mma_gemm_h<128, 0, false, true>,  cudaFuncAttributeMaxDynamicSharedMemorySize, SM128);
    cudaFuncSetAttribute((const void*)mma_gemm_h<128, 1, true,  false>, cudaFuncAttributeMaxDynamicSharedMemorySize, SM128);
    cudaFuncSetAttribute((const void*)mma_gemm_h<128, 2, true,  false>, cudaFuncAttributeMaxDynamicSharedMemorySize, SM128);
    cudaFuncSetAttribute((const void*)mma_gemm_h<128, 3, false, true>,  cudaFuncAttributeMaxDynamicSharedMemorySize, SM128);
    cudaFuncSetAttribute((const void*)mma_gemm_h<64,  0, false, true>,  cudaFuncAttributeMaxDynamicSharedMemorySize, SM64);

    dim3 tb(32, 8);

    // 0) fp16 conversions (weights + q)
    f2h_kernel<<<(BB * NQ * CC) / 1024, 256>>>(q,  q16,  BB * NQ * CC);
    f2h_kernel<<<(CC * CC) / 1024, 256>>>(Wq,    wq16,  CC * CC);
    f2h_kernel<<<(CC * 2 * CC) / 1024, 256>>>(Wkv, wkv16, CC * 2 * CC);
    f2h_kernel<<<(CC * CC) / 1024, 256>>>(Wproj, wp16,  CC * CC);
    f2h_kernel<<<(CC * HID) / 1024, 256>>>(W1,   w116,  CC * HID);
    f2h_kernel<<<(HID * CC) / 1024, 256>>>(W2,   w216,  HID * CC);

    // 1) xn16 = LN(x)
    ln_kernel_h<<<BB * NKV, 256>>>(x, g1, be1, xn16, CC);

    // 2) qh16 = q16 @ Wq16
    mma_gemm_h<128, 0, false, true><<<dim3(CC / 128, BB * NQ / 128, 1), 256, SM128>>>(
        q16, CC, 0, 0, wq16, CC, 0, 0, nullptr, qh16, CC, 0, 0, CC, nullptr, nullptr, 0, 0.f);

    // 3) kv16 = xn16 @ Wkv16
    mma_gemm_h<128, 0, false, true><<<dim3(2 * CC / 128, BB * NKV / 128, 1), 256, SM128>>>(
        xn16, CC, 0, 0, wkv16, 2 * CC, 0, 0, nullptr, kv16, 2 * CC, 0, 0, CC, nullptr, nullptr, 0, 0.f);

    // 4) kT16 = transpose of k-half of kv16
    transpose_h<<<dim3(CC / 32, NKV / 32, BB), tb>>>(
        kv16, 2 * CC, (long)NKV * 2 * CC, kT16, NKV, (long)CC * NKV);

    // 5) scores -> out_attn fp32 (scaled)
    mma_gemm_h<128, 1, true, false><<<dim3(NKV / 128, NQ / 128, BB * NH), 256, SM128>>>(
        qh16, CC, (long)NQ * CC, DH,
        kT16, NKV, (long)CC * NKV, (long)DH * NKV,
        out_attn, nullptr, NKV, (long)NH * NQ * NKV, (long)NQ * NKV,
        DH, nullptr, nullptr, 0, 0.125f);

    // 6) softmax: fp32 in-place + fp16 copy
    softmax_kernel<<<BB * NH * NQ, 256>>>(out_attn, at16);

    // 7) y16 = attn16 @ V16
    mma_gemm_h<64, 0, false, true><<<dim3(1, NQ / 128, BB * NH), 256, SM64>>>(
        at16, NKV, (long)NH * NQ * NKV, (long)NQ * NKV,
        kv16 + CC, 2 * CC, (long)NKV * 2 * CC, DH,
        nullptr, y16, CC, (long)NQ * CC, DH,
        NKV, nullptr, nullptr, 0, 0.f);

    // 8) q2 = q + y16 @ Wp16 + bproj   (fp32)
    mma_gemm_h<128, 2, true, false><<<dim3(CC / 128, BB * NQ / 128, 1), 256, SM128>>>(
        y16, CC, 0, 0, wp16, CC, 0, 0, q2, nullptr, CC, 0, 0, CC, bproj, q, CC, 0.f);

    // 9) t16 = LN(q2)
    ln_kernel_h<<<BB * NQ, 256>>>(q2, g2, be2, t16, CC);

    // 10) hid16 = gelu(t16 @ W116 + b1)
    mma_gemm_h<128, 3, false, true><<<dim3(HID / 128, BB * NQ / 128, 1), 256, SM128>>>(
        t16, CC, 0, 0, w116, HID, 0, 0, nullptr, hid16, HID, 0, 0, CC, b1, nullptr, 0, 0.f);

    // 11) out_q = q2 + hid16 @ W216 + b2   (fp32)
    mma_gemm_h<128, 2, true, false><<<dim3(CC / 128, BB * NQ / 128, 1), 256, SM128>>>(
        hid16, HID, 0, 0, w216, CC, 0, 0, out_q, nullptr, CC, 0, 0, HID, b2, q2, CC, 0.f);
}

// round 7
// speedup vs baseline: 5.5206x; 1.0634x over previous
#include <cuda_runtime.h>
#include <cuda_fp16.h>
#include <cstdint>
#include <math.h>

#define BB   4
#define NQ   1024
#define NKV  2048
#define CC   1024
#define NH   16
#define DH   64
#define HID  4096

// ---------------- scratch (device globals; allocation-guard safe) -----------
__device__ __half g_q16 [BB * NQ * CC];
__device__ __half g_xn16[BB * NKV * CC];
__device__ __half g_qh16[BB * NQ * CC];
__device__ __half g_kv16[BB * NKV * 2 * CC];
__device__ __half g_kT16[BB * CC * NKV];
__device__ __half g_at16[(size_t)BB * NH * NQ * NKV];
__device__ __half g_y16 [BB * NQ * CC];
__device__ __half g_t16 [BB * NQ * CC];
__device__ __half g_hid16[BB * NQ * HID];
__device__ float  g_q2  [BB * NQ * CC];
__device__ float  g_rowsum[BB * NH * NQ];
__device__ __half g_wq16 [CC * CC];
__device__ __half g_wkv16[CC * 2 * CC];
__device__ __half g_wp16 [CC * CC];
__device__ __half g_w116 [CC * HID];
__device__ __half g_w216 [HID * CC];

// ---------------------------------------------------------------------------
__device__ __forceinline__ uint32_t smem_u32(const void* p) {
    uint32_t a;
    asm("{ .reg .u64 t; cvta.to.shared.u64 t, %1; cvt.u32.u64 %0, t; }" : "=r"(a) : "l"(p));
    return a;
}
__device__ __forceinline__ uint32_t packh2(float x, float y) {
    uint32_t u;
    asm("cvt.rn.f16x2.f32 %0, %1, %2;" : "=r"(u) : "f"(y), "f"(x));
    return u;
}
__device__ __forceinline__ void cpasync16(uint32_t dst, const void* src) {
    asm volatile("cp.async.ca.shared.global [%0], [%1], 16;" :: "r"(dst), "l"(src));
}
#define CP_COMMIT() asm volatile("cp.async.commit_group;" ::: "memory")
#define CP_WAIT(N)  asm volatile("cp.async.wait_group %0;" :: "n"(N) : "memory")

__device__ __forceinline__ void mma_f16(float* c, const uint32_t* a, const uint32_t* b) {
    asm volatile(
        "mma.sync.aligned.m16n8k16.row.col.f32.f16.f16.f32 "
        "{%0,%1,%2,%3}, {%4,%5,%6,%7}, {%8,%9}, {%0,%1,%2,%3};"
        : "+f"(c[0]), "+f"(c[1]), "+f"(c[2]), "+f"(c[3])
        : "r"(a[0]), "r"(a[1]), "r"(a[2]), "r"(a[3]), "r"(b[0]), "r"(b[1]));
}
#define LDSM_X4(r0, r1, r2, r3, addr) \
    asm volatile("ldmatrix.sync.aligned.m8n8.x4.shared.b16 {%0,%1,%2,%3}, [%4];" \
                 : "=r"(r0), "=r"(r1), "=r"(r2), "=r"(r3) : "r"(addr))
#define LDSM_X4T(r0, r1, r2, r3, addr) \
    asm volatile("ldmatrix.sync.aligned.m8n8.x4.trans.shared.b16 {%0,%1,%2,%3}, [%4];" \
                 : "=r"(r0), "=r"(r1), "=r"(r2), "=r"(r3) : "r"(addr))

// ---------------------------------------------------------------------------
// fp16 tensor-core GEMM, cp.async 3-stage pipeline.
// C[128 x BN] tile of A[M,K] @ B[K,N], f32 accumulate. A,B fp16 in GMEM.
// MODE 0: v=acc  2: v=acc+bias[n]+res  3: v=gelu(acc+bias[n])
// MODE 4: v=exp(acc*scale)/rowsum[row]  (res = rowsum base, [z*NQ + m])
// WF: write float Cf; WH: write half Ch (same strides).
// ---------------------------------------------------------------------------
template <int BN, int MODE, bool WF, bool WH>
__global__ __launch_bounds__(256) void mma_gemm_h(
    const __half* __restrict__ A, int lda, long saB, long saH,
    const __half* __restrict__ B, int ldb, long sbB, long sbH,
    float* __restrict__ Cf, __half* __restrict__ Ch, int ldc, long scB, long scH,
    int K, const float* __restrict__ bias,
    const float* __restrict__ res, int ldres, float scale)
{
    constexpr int S    = 3;
    constexpr int APH  = 40;               // A smem pitch (halves) -> 80 B
    constexpr int BPH  = BN + 8;           // B smem pitch (halves)
    constexpr int ABUF = 128 * APH * 2;
    constexpr int BBUF = 32 * BPH * 2;
    constexpr int STG  = ABUF + BBUF;
    constexpr int WC   = (BN == 128) ? 4 : 2;
    constexpr int WM   = (BN == 128) ? 64 : 32;
    constexpr int MT   = WM / 16;
    constexpr int NT   = 4;
    constexpr int BCH  = BN / 64;          // B chunks per thread (2 or 1)
    constexpr int BROWCH = BN / 8;         // 16B chunks per B row

    extern __shared__ __align__(16) char smem[];
    const uint32_t sb0 = smem_u32(smem);

    const int tid  = threadIdx.x;
    const int wid  = tid >> 5;
    const int lane = tid & 31;
    const int wm   = (wid / WC) * WM;
    const int wn   = (wid % WC) * 32;

    const int z = blockIdx.z, zb = z >> 4, zh = z & 15;
    const int bm = blockIdx.y * 128, bn = blockIdx.x * BN;

    const __half* Ab = A + (long)zb * saB + (long)zh * saH + (size_t)bm * lda;
    const __half* Bb = B + (long)zb * sbB + (long)zh * sbH + bn;
    float*  Cfb = WF ? Cf + (long)zb * scB + (long)zh * scH + (size_t)bm * ldc + bn : nullptr;
    __half* Chb = WH ? Ch + (long)zb * scB + (long)zh * scH + (size_t)bm * ldc + bn : nullptr;
    const float* Rb = (MODE == 2) ? res + (size_t)bm * ldres + bn : nullptr;
    const float* Rv = (MODE == 4) ? res + (long)z * NQ + bm : nullptr;

    const int nchunk = K >> 5;

    auto issue = [&](int ci) {
        const int s = ci % S;
        const uint32_t sA = sb0 + s * STG;
        const uint32_t sB = sA + ABUF;
        const int k0 = ci * 32;
        #pragma unroll
        for (int u = 0; u < 2; u++) {
            int c = tid + u * 256;
            int row = c >> 2, col = c & 3;
            cpasync16(sA + row * 80 + col * 16,
                      Ab + (size_t)row * lda + k0 + col * 8);
        }
        #pragma unroll
        for (int u = 0; u < BCH; u++) {
            int c = tid + u * 256;
            int row = c / BROWCH, col = c % BROWCH;
            cpasync16(sB + row * (BPH * 2) + col * 16,
                      Bb + (size_t)(k0 + row) * ldb + col * 8);
        }
        CP_COMMIT();
    };

    #pragma unroll
    for (int s = 0; s < S - 1; s++)
        if (s < nchunk) issue(s);

    float acc[MT][NT][4];
    #pragma unroll
    for (int i = 0; i < MT; i++)
        #pragma unroll
        for (int j = 0; j < NT; j++)
            #pragma unroll
            for (int v = 0; v < 4; v++) acc[i][j][v] = 0.f;

    const int lr = ((lane >> 3) & 1) * 8 + (lane & 7);
    const int lc = ((lane >> 4) & 1) * 8;

    for (int ci = 0; ci < nchunk; ci++) {
        if (ci + 2 < nchunk) { CP_WAIT(1); } else { CP_WAIT(0); }
        __syncthreads();
        if (ci + 2 < nchunk) issue(ci + 2);

        const uint32_t sA = sb0 + (ci % S) * STG;
        const uint32_t sB = sA + ABUF;
        #pragma unroll
        for (int kk = 0; kk < 2; kk++) {
            uint32_t af[MT][4], bf[2][4];
            #pragma unroll
            for (int i = 0; i < MT; i++) {
                uint32_t addr = sA + (uint32_t)(((wm + 16 * i + lr) * APH + kk * 16 + lc) * 2);
                LDSM_X4(af[i][0], af[i][1], af[i][2], af[i][3], addr);
            }
            #pragma unroll
            for (int jj = 0; jj < 2; jj++) {
                uint32_t addr = sB + (uint32_t)(((kk * 16 + lr) * BPH + wn + 16 * jj + lc) * 2);
                LDSM_X4T(bf[jj][0], bf[jj][1], bf[jj][2], bf[jj][3], addr);
            }
            #pragma unroll
            for (int i = 0; i < MT; i++) {
                #pragma unroll
                for (int jj = 0; jj < 2; jj++) {
                    mma_f16(acc[i][2 * jj + 0], af[i], &bf[jj][0]);
                    mma_f16(acc[i][2 * jj + 1], af[i], &bf[jj][2]);
                }
            }
        }
        __syncthreads();
    }

    // epilogue
    const int er = lane >> 2, ec = (lane & 3) * 2;
    #pragma unroll
    for (int i = 0; i < MT; i++) {
        #pragma unroll
        for (int rr = 0; rr < 2; rr++) {
            const int row = wm + 16 * i + er + 8 * rr;
            float*  Cfrow = WF ? Cfb + (size_t)row * ldc : nullptr;
            __half* Chrow = WH ? Chb + (size_t)row * ldc : nullptr;
            const float* Rrow = (MODE == 2) ? Rb + (size_t)row * ldres : nullptr;
            float inv = 0.f;
            if (MODE == 4) inv = 1.0f / Rv[row];
            #pragma unroll
            for (int j = 0; j < NT; j++) {
                const int col = wn + 8 * j + ec;
                float v0 = acc[i][j][2 * rr + 0];
                float v1 = acc[i][j][2 * rr + 1];
                if (MODE == 2) {
                    v0 += bias[bn + col]     + Rrow[col];
                    v1 += bias[bn + col + 1] + Rrow[col + 1];
                }
                if (MODE == 3) {
                    v0 += bias[bn + col];
                    v1 += bias[bn + col + 1];
                    v0 = 0.5f * v0 * (1.0f + erff(v0 * 0.70710678118654752f));
                    v1 = 0.5f * v1 * (1.0f + erff(v1 * 0.70710678118654752f));
                }
                if (MODE == 4) {
                    v0 = __expf(v0 * scale) * inv;
                    v1 = __expf(v1 * scale) * inv;
                }
                if (WF) *(float2*)&Cfrow[col] = make_float2(v0, v1);
                if (WH) *(uint32_t*)&Chrow[col] = packh2(v0, v1);
            }
        }
    }
}

// ---------------------------------------------------------------------------
// Pass 1: rowsum[z, m] = sum_n exp(scale * (qh[z,m,:] . kT[z,:,n]))
// One CTA per (128 q-rows, b*h). Streams 16 chunks of 128 KV columns.
// Same mma ordering as the MODE-4 pass for consistency. No atomics.
// ---------------------------------------------------------------------------
__global__ __launch_bounds__(256) void score_sum_kernel(
    const __half* __restrict__ qh, const __half* __restrict__ kT,
    float* __restrict__ rowsum)
{
    constexpr int APH = 72;                 // A pitch (halves): 144 B rows
    constexpr int BPH = 136;                // B pitch (halves): 272 B rows
    constexpr int ABUF = 128 * APH * 2;     // 18432
    constexpr int BBUF = 64 * BPH * 2;      // 17408

    extern __shared__ __align__(16) char smem[];
    const uint32_t sA  = smem_u32(smem);
    const uint32_t sB0 = sA + ABUF;
    float* wsum = (float*)(smem + ABUF + 2 * BBUF);   // [4][128]

    const int tid = threadIdx.x, wid = tid >> 5, lane = tid & 31;
    const int wm = (wid >> 2) * 64, wn = (wid & 3) * 32;
    const int qb = blockIdx.x, z = blockIdx.y;
    const int zb = z >> 4, zh = z & 15;

    const __half* Ab = qh + (size_t)zb * NQ * CC + zh * DH + (size_t)(qb * 128) * CC;
    const __half* Bb = kT + (size_t)zb * CC * NKV + (size_t)zh * DH * NKV;

    // A load (one group): 128 rows x 64 halves
    #pragma unroll
    for (int u = 0; u < 4; u++) {
        int c = tid + u * 256;
        int row = c >> 3, col = c & 7;
        cpasync16(sA + row * (APH * 2) + col * 16, Ab + (size_t)row * CC + col * 8);
    }
    CP_COMMIT();

    auto issueB = [&](int c) {
        const uint32_t dst = sB0 + (c & 1) * BBUF;
        #pragma unroll
        for (int u = 0; u < 4; u++) {
            int idx = tid + u * 256;
            int row = idx >> 4, col = idx & 15;
            cpasync16(dst + row * (BPH * 2) + col * 16,
                      Bb + (size_t)row * NKV + c * 128 + col * 8);
        }
        CP_COMMIT();
    };
    issueB(0);

    const int lr = ((lane >> 3) & 1) * 8 + (lane & 7);
    const int lc = ((lane >> 4) & 1) * 8;

    float rp[4][2];
    #pragma unroll
    for (int i = 0; i < 4; i++) { rp[i][0] = 0.f; rp[i][1] = 0.f; }

    for (int c = 0; c < 16; c++) {
        if (c + 1 < 16) { issueB(c + 1); CP_WAIT(1); } else { CP_WAIT(0); }
        __syncthreads();
        const uint32_t sB = sB0 + (c & 1) * BBUF;

        float acc[4][4][4];
        #pragma unroll
        for (int i = 0; i < 4; i++)
            #pragma unroll
            for (int j = 0; j < 4; j++)
                #pragma unroll
                for (int v = 0; v < 4; v++) acc[i][j][v] = 0.f;

        #pragma unroll
        for (int kst = 0; kst < 4; kst++) {
            uint32_t af[4][4], bf[2][4];
            #pragma unroll
            for (int i = 0; i < 4; i++) {
                uint32_t addr = sA + (uint32_t)(((wm + 16 * i + lr) * APH + kst * 16 + lc) * 2);
                LDSM_X4(af[i][0], af[i][1], af[i][2], af[i][3], addr);
            }
            #pragma unroll
            for (int jj = 0; jj < 2; jj++) {
                uint32_t addr = sB + (uint32_t)(((kst * 16 + lr) * BPH + wn + 16 * jj + lc) * 2);
                LDSM_X4T(bf[jj][0], bf[jj][1], bf[jj][2], bf[jj][3], addr);
            }
            #pragma unroll
            for (int i = 0; i < 4; i++) {
                #pragma unroll
                for (int jj = 0; jj < 2; jj++) {
                    mma_f16(acc[i][2 * jj + 0], af[i], &bf[jj][0]);
                    mma_f16(acc[i][2 * jj + 1], af[i], &bf[jj][2]);
                }
            }
        }

        #pragma unroll
        for (int i = 0; i < 4; i++)
            #pragma unroll
            for (int j = 0; j < 4; j++) {
                rp[i][0] += __expf(acc[i][j][0] * 0.125f) + __expf(acc[i][j][1] * 0.125f);
                rp[i][1] += __expf(acc[i][j][2] * 0.125f) + __expf(acc[i][j][3] * 0.125f);
            }
        __syncthreads();
    }

    // reduce across the 4 lanes of each quad (columns within fragment)
    #pragma unroll
    for (int i = 0; i < 4; i++)
        #pragma unroll
        for (int rr = 0; rr < 2; rr++) {
            float v = rp[i][rr];
            v += __shfl_xor_sync(~0u, v, 1);
            v += __shfl_xor_sync(~0u, v, 2);
            rp[i][rr] = v;
        }
    if ((lane & 3) == 0) {
        int er = lane >> 2;
        #pragma unroll
        for (int i = 0; i < 4; i++)
            #pragma unroll
            for (int rr = 0; rr < 2; rr++)
                wsum[(wid & 3) * 128 + wm + 16 * i + 8 * rr + er] = rp[i][rr];
    }
    __syncthreads();
    if (tid < 128) {
        float s = wsum[tid] + wsum[128 + tid] + wsum[256 + tid] + wsum[384 + tid];
        rowsum[(size_t)z * NQ + qb * 128 + tid] = s;
    }
}

// ---------------------------------------------------------------------------
__global__ void f2h_kernel(const float* __restrict__ in, __half* __restrict__ out, int n)
{
    int i = (blockIdx.x * blockDim.x + threadIdx.x) * 4;
    if (i < n) {
        float4 v = *(const float4*)(in + i);
        uint2 u = { packh2(v.x, v.y), packh2(v.z, v.w) };
        *(uint2*)(out + i) = u;
    }
}

// ---------------------------------------------------------------------------
__global__ void transpose_h(const __half* __restrict__ in, int ld_in, long sb_in,
                            __half* __restrict__ out, int ld_out, long sb_out)
{
    __shared__ __half tile[32][34];
    const __half* ip = in + (long)blockIdx.z * sb_in;
    __half* op = out + (long)blockIdx.z * sb_out;
    int r0 = blockIdx.y * 32, c0 = blockIdx.x * 32;
    int x = threadIdx.x, y = threadIdx.y;
    #pragma unroll
    for (int j = 0; j < 32; j += 8)
        tile[y + j][x] = ip[(size_t)(r0 + y + j) * ld_in + c0 + x];
    __syncthreads();
    #pragma unroll
    for (int j = 0; j < 32; j += 8)
        op[(size_t)(c0 + y + j) * ld_out + r0 + x] = tile[x][y + j];
}

// ---------------------------------------------------------------------------
__global__ void ln_kernel_h(const float* __restrict__ x, const float* __restrict__ g,
                            const float* __restrict__ be, __half* __restrict__ out, int ccols)
{
    int row = blockIdx.x;
    const float* p = x + (size_t)row * ccols;
    __half* o = out + (size_t)row * ccols;
    int t = threadIdx.x;

    float s = 0.f, s2 = 0.f;
    for (int i = t; i < ccols; i += blockDim.x) { float v = p[i]; s += v; s2 += v * v; }
    __shared__ float r1[8], r2[8];
    #pragma unroll
    for (int off = 16; off; off >>= 1) {
        s  += __shfl_xor_sync(~0u, s,  off);
        s2 += __shfl_xor_sync(~0u, s2, off);
    }
    if ((t & 31) == 0) { r1[t >> 5] = s; r2[t >> 5] = s2; }
    __syncthreads();
    float ts = 0.f, ts2 = 0.f;
    #pragma unroll
    for (int i = 0; i < 8; i++) { ts += r1[i]; ts2 += r2[i]; }
    float mean = ts / ccols;
    float var  = ts2 / ccols - mean * mean;
    float inv  = rsqrtf(var + 1e-5f);
    for (int i = t; i < ccols; i += blockDim.x)
        o[i] = __float2half((p[i] - mean) * inv * g[i] + be[i]);
}

// ---------------------------------------------------------------------------
extern "C" void kernel_launch(void* const* d_in, const int* in_sizes, int n_in,
                              void* d_out, int out_size)
{
    const float* q     = (const float*)d_in[0];
    const float* x     = (const float*)d_in[1];
    const float* Wq    = (const float*)d_in[2];
    const float* Wkv   = (const float*)d_in[3];
    const float* Wproj = (const float*)d_in[4];
    const float* bproj = (const float*)d_in[5];
    const float* W1    = (const float*)d_in[6];
    const float* b1    = (const float*)d_in[7];
    const float* W2    = (const float*)d_in[8];
    const float* b2    = (const float*)d_in[9];
    const float* g1    = (const float*)d_in[10];
    const float* be1   = (const float*)d_in[11];
    const float* g2    = (const float*)d_in[12];
    const float* be2   = (const float*)d_in[13];

    float* out_q    = (float*)d_out;
    float* out_attn = out_q + (size_t)BB * NQ * CC;

    __half *q16, *xn16, *qh16, *kv16, *kT16, *at16, *y16, *t16, *hid16;
    __half *wq16, *wkv16, *wp16, *w116, *w216;
    float  *q2, *rowsum;
    cudaGetSymbolAddress((void**)&q16,  g_q16);
    cudaGetSymbolAddress((void**)&xn16, g_xn16);
    cudaGetSymbolAddress((void**)&qh16, g_qh16);
    cudaGetSymbolAddress((void**)&kv16, g_kv16);
    cudaGetSymbolAddress((void**)&kT16, g_kT16);
    cudaGetSymbolAddress((void**)&at16, g_at16);
    cudaGetSymbolAddress((void**)&y16,  g_y16);
    cudaGetSymbolAddress((void**)&t16,  g_t16);
    cudaGetSymbolAddress((void**)&hid16,g_hid16);
    cudaGetSymbolAddress((void**)&q2,   g_q2);
    cudaGetSymbolAddress((void**)&rowsum, g_rowsum);
    cudaGetSymbolAddress((void**)&wq16, g_wq16);
    cudaGetSymbolAddress((void**)&wkv16,g_wkv16);
    cudaGetSymbolAddress((void**)&wp16, g_wp16);
    cudaGetSymbolAddress((void**)&w116, g_w116);
    cudaGetSymbolAddress((void**)&w216, g_w216);

    const int SM128 = 3 * (128 * 40 * 2 + 32 * 136 * 2);   // 56832
    const int SM64  = 3 * (128 * 40 * 2 + 32 * 72 * 2);    // 44544
    const int SMS   = 128 * 72 * 2 + 2 * 64 * 136 * 2 + 4 * 128 * 4;  // 55296
    cudaFuncSetAttribute((const void*)mma_gemm_h<128, 0, false, true>,  cudaFuncAttributeMaxDynamicSharedMemorySize, SM128);
    cudaFuncSetAttribute((const void*)mma_gemm_h<128, 2, true,  false>, cudaFuncAttributeMaxDynamicSharedMemorySize, SM128);
    cudaFuncSetAttribute((const void*)mma_gemm_h<128, 3, false, true>,  cudaFuncAttributeMaxDynamicSharedMemorySize, SM128);
    cudaFuncSetAttribute((const void*)mma_gemm_h<128, 4, true,  true>,  cudaFuncAttributeMaxDynamicSharedMemorySize, SM128);
    cudaFuncSetAttribute((const void*)mma_gemm_h<64,  0, false, true>,  cudaFuncAttributeMaxDynamicSharedMemorySize, SM64);
    cudaFuncSetAttribute((const void*)score_sum_kernel, cudaFuncAttributeMaxDynamicSharedMemorySize, SMS);

    dim3 tb(32, 8);

    // 0) fp16 conversions (weights + q)
    f2h_kernel<<<(BB * NQ * CC) / 1024, 256>>>(q,  q16,  BB * NQ * CC);
    f2h_kernel<<<(CC * CC) / 1024, 256>>>(Wq,    wq16,  CC * CC);
    f2h_kernel<<<(CC * 2 * CC) / 1024, 256>>>(Wkv, wkv16, CC * 2 * CC);
    f2h_kernel<<<(CC * CC) / 1024, 256>>>(Wproj, wp16,  CC * CC);
    f2h_kernel<<<(CC * HID) / 1024, 256>>>(W1,   w116,  CC * HID);
    f2h_kernel<<<(HID * CC) / 1024, 256>>>(W2,   w216,  HID * CC);

    // 1) xn16 = LN(x)
    ln_kernel_h<<<BB * NKV, 256>>>(x, g1, be1, xn16, CC);

    // 2) qh16 = q16 @ Wq16
    mma_gemm_h<128, 0, false, true><<<dim3(CC / 128, BB * NQ / 128, 1), 256, SM128>>>(
        q16, CC, 0, 0, wq16, CC, 0, 0, nullptr, qh16, CC, 0, 0, CC, nullptr, nullptr, 0, 0.f);

    // 3) kv16 = xn16 @ Wkv16
    mma_gemm_h<128, 0, false, true><<<dim3(2 * CC / 128, BB * NKV / 128, 1), 256, SM128>>>(
        xn16, CC, 0, 0, wkv16, 2 * CC, 0, 0, nullptr, kv16, 2 * CC, 0, 0, CC, nullptr, nullptr, 0, 0.f);

    // 4) kT16 = transpose of k-half of kv16
    transpose_h<<<dim3(CC / 32, NKV / 32, BB), tb>>>(
        kv16, 2 * CC, (long)NKV * 2 * CC, kT16, NKV, (long)CC * NKV);

    // 5a) rowsum[z, m] = sum_n exp(s/8)
    score_sum_kernel<<<dim3(NQ / 128, BB * NH), 256, SMS>>>(qh16, kT16, rowsum);

    // 5b) attn = exp(s/8)/rowsum -> fp32 out_attn + fp16 at16
    mma_gemm_h<128, 4, true, true><<<dim3(NKV / 128, NQ / 128, BB * NH), 256, SM128>>>(
        qh16, CC, (long)NQ * CC, DH,
        kT16, NKV, (long)CC * NKV, (long)DH * NKV,
        out_attn, at16, NKV, (long)NH * NQ * NKV, (long)NQ * NKV,
        DH, nullptr, rowsum, 0, 0.125f);

    // 6) y16 = attn16 @ V16
    mma_gemm_h<64, 0, false, true><<<dim3(1, NQ / 128, BB * NH), 256, SM64>>>(
        at16, NKV, (long)NH * NQ * NKV, (long)NQ * NKV,
        kv16 + CC, 2 * CC, (long)NKV * 2 * CC, DH,
        nullptr, y16, CC, (long)NQ * CC, DH,
        NKV, nullptr, nullptr, 0, 0.f);

    // 7) q2 = q + y16 @ Wp16 + bproj   (fp32)
    mma_gemm_h<128, 2, true, false><<<dim3(CC / 128, BB * NQ / 128, 1), 256, SM128>>>(
        y16, CC, 0, 0, wp16, CC, 0, 0, q2, nullptr, CC, 0, 0, CC, bproj, q, CC, 0.f);

    // 8) t16 = LN(q2)
    ln_kernel_h<<<BB * NQ, 256>>>(q2, g2, be2, t16, CC);

    // 9) hid16 = gelu(t16 @ W116 + b1)
    mma_gemm_h<128, 3, false, true><<<dim3(HID / 128, BB * NQ / 128, 1), 256, SM128>>>(
        t16, CC, 0, 0, w116, HID, 0, 0, nullptr, hid16, HID, 0, 0, CC, b1, nullptr, 0, 0.f);

    // 10) out_q = q2 + hid16 @ W216 + b2   (fp32)
    mma_gemm_h<128, 2, true, false><<<dim3(CC / 128, BB * NQ / 128, 1), 256, SM128>>>(
        hid16, HID, 0, 0, w216, CC, 0, 0, out_q, nullptr, CC, 0, 0, HID, b2, q2, CC, 0.f);
}

// round 8
// speedup vs baseline: 6.2635x; 1.1346x over previous
#include <cuda_runtime.h>
#include <cuda_fp16.h>
#include <cstdint>
#include <math.h>

#define BB   4
#define NQ   1024
#define NKV  2048
#define CC   1024
#define NH   16
#define DH   64
#define HID  4096

// ---------------- scratch (device globals; allocation-guard safe) -----------
__device__ __half g_q16 [BB * NQ * CC];
__device__ __half g_xn16[BB * NKV * CC];
__device__ __half g_qh16[BB * NQ * CC];
__device__ __half g_kv16[BB * NKV * 2 * CC];
__device__ __half g_kT16[BB * CC * NKV];
__device__ __half g_y16 [BB * NQ * CC];
__device__ __half g_t16 [BB * NQ * CC];
__device__ __half g_hid16[BB * NQ * HID];
__device__ float  g_q2  [BB * NQ * CC];
__device__ float  g_rowsum[BB * NH * NQ];
__device__ __half g_wq16 [CC * CC];
__device__ __half g_wkv16[CC * 2 * CC];
__device__ __half g_wp16 [CC * CC];
__device__ __half g_w116 [CC * HID];
__device__ __half g_w216 [HID * CC];

// ---------------------------------------------------------------------------
__device__ __forceinline__ uint32_t smem_u32(const void* p) {
    uint32_t a;
    asm("{ .reg .u64 t; cvta.to.shared.u64 t, %1; cvt.u32.u64 %0, t; }" : "=r"(a) : "l"(p));
    return a;
}
__device__ __forceinline__ uint32_t packh2(float x, float y) {
    uint32_t u;
    asm("cvt.rn.f16x2.f32 %0, %1, %2;" : "=r"(u) : "f"(y), "f"(x));
    return u;
}
__device__ __forceinline__ void cpasync16(uint32_t dst, const void* src) {
    asm volatile("cp.async.ca.shared.global [%0], [%1], 16;" :: "r"(dst), "l"(src));
}
#define CP_COMMIT() asm volatile("cp.async.commit_group;" ::: "memory")
#define CP_WAIT(N)  asm volatile("cp.async.wait_group %0;" :: "n"(N) : "memory")

__device__ __forceinline__ void mma_f16(float* c, const uint32_t* a, const uint32_t* b) {
    asm volatile(
        "mma.sync.aligned.m16n8k16.row.col.f32.f16.f16.f32 "
        "{%0,%1,%2,%3}, {%4,%5,%6,%7}, {%8,%9}, {%0,%1,%2,%3};"
        : "+f"(c[0]), "+f"(c[1]), "+f"(c[2]), "+f"(c[3])
        : "r"(a[0]), "r"(a[1]), "r"(a[2]), "r"(a[3]), "r"(b[0]), "r"(b[1]));
}
#define LDSM_X4(r0, r1, r2, r3, addr) \
    asm volatile("ldmatrix.sync.aligned.m8n8.x4.shared.b16 {%0,%1,%2,%3}, [%4];" \
                 : "=r"(r0), "=r"(r1), "=r"(r2), "=r"(r3) : "r"(addr))
#define LDSM_X4T(r0, r1, r2, r3, addr) \
    asm volatile("ldmatrix.sync.aligned.m8n8.x4.trans.shared.b16 {%0,%1,%2,%3}, [%4];" \
                 : "=r"(r0), "=r"(r1), "=r"(r2), "=r"(r3) : "r"(addr))

// ---------------------------------------------------------------------------
// fp16 tensor-core GEMM, cp.async 3-stage pipeline.
// MODE 0: v=acc  2: v=acc+bias[n]+res  3: v=gelu(acc+bias[n])
// MODE 4: v=exp(acc*scale)/rowsum[row]  (res = rowsum base, [z*NQ + m])
// ---------------------------------------------------------------------------
template <int BN, int MODE, bool WF, bool WH>
__global__ __launch_bounds__(256) void mma_gemm_h(
    const __half* __restrict__ A, int lda, long saB, long saH,
    const __half* __restrict__ B, int ldb, long sbB, long sbH,
    float* __restrict__ Cf, __half* __restrict__ Ch, int ldc, long scB, long scH,
    int K, const float* __restrict__ bias,
    const float* __restrict__ res, int ldres, float scale)
{
    constexpr int S    = 3;
    constexpr int APH  = 40;
    constexpr int BPH  = BN + 8;
    constexpr int ABUF = 128 * APH * 2;
    constexpr int BBUF = 32 * BPH * 2;
    constexpr int STG  = ABUF + BBUF;
    constexpr int WC   = (BN == 128) ? 4 : 2;
    constexpr int WM   = (BN == 128) ? 64 : 32;
    constexpr int MT   = WM / 16;
    constexpr int NT   = 4;
    constexpr int BCH  = BN / 64;
    constexpr int BROWCH = BN / 8;

    extern __shared__ __align__(16) char smem[];
    const uint32_t sb0 = smem_u32(smem);

    const int tid  = threadIdx.x;
    const int wid  = tid >> 5;
    const int lane = tid & 31;
    const int wm   = (wid / WC) * WM;
    const int wn   = (wid % WC) * 32;

    const int z = blockIdx.z, zb = z >> 4, zh = z & 15;
    const int bm = blockIdx.y * 128, bn = blockIdx.x * BN;

    const __half* Ab = A + (long)zb * saB + (long)zh * saH + (size_t)bm * lda;
    const __half* Bb = B + (long)zb * sbB + (long)zh * sbH + bn;
    float*  Cfb = WF ? Cf + (long)zb * scB + (long)zh * scH + (size_t)bm * ldc + bn : nullptr;
    __half* Chb = WH ? Ch + (long)zb * scB + (long)zh * scH + (size_t)bm * ldc + bn : nullptr;
    const float* Rb = (MODE == 2) ? res + (size_t)bm * ldres + bn : nullptr;
    const float* Rv = (MODE == 4) ? res + (long)z * NQ + bm : nullptr;

    const int nchunk = K >> 5;

    auto issue = [&](int ci) {
        const int s = ci % S;
        const uint32_t sA = sb0 + s * STG;
        const uint32_t sB = sA + ABUF;
        const int k0 = ci * 32;
        #pragma unroll
        for (int u = 0; u < 2; u++) {
            int c = tid + u * 256;
            int row = c >> 2, col = c & 3;
            cpasync16(sA + row * 80 + col * 16,
                      Ab + (size_t)row * lda + k0 + col * 8);
        }
        #pragma unroll
        for (int u = 0; u < BCH; u++) {
            int c = tid + u * 256;
            int row = c / BROWCH, col = c % BROWCH;
            cpasync16(sB + row * (BPH * 2) + col * 16,
                      Bb + (size_t)(k0 + row) * ldb + col * 8);
        }
        CP_COMMIT();
    };

    #pragma unroll
    for (int s = 0; s < S - 1; s++)
        if (s < nchunk) issue(s);

    float acc[MT][NT][4];
    #pragma unroll
    for (int i = 0; i < MT; i++)
        #pragma unroll
        for (int j = 0; j < NT; j++)
            #pragma unroll
            for (int v = 0; v < 4; v++) acc[i][j][v] = 0.f;

    const int lr = ((lane >> 3) & 1) * 8 + (lane & 7);
    const int lc = ((lane >> 4) & 1) * 8;

    for (int ci = 0; ci < nchunk; ci++) {
        if (ci + 2 < nchunk) { CP_WAIT(1); } else { CP_WAIT(0); }
        __syncthreads();
        if (ci + 2 < nchunk) issue(ci + 2);

        const uint32_t sA = sb0 + (ci % S) * STG;
        const uint32_t sB = sA + ABUF;
        #pragma unroll
        for (int kk = 0; kk < 2; kk++) {
            uint32_t af[MT][4], bf[2][4];
            #pragma unroll
            for (int i = 0; i < MT; i++) {
                uint32_t addr = sA + (uint32_t)(((wm + 16 * i + lr) * APH + kk * 16 + lc) * 2);
                LDSM_X4(af[i][0], af[i][1], af[i][2], af[i][3], addr);
            }
            #pragma unroll
            for (int jj = 0; jj < 2; jj++) {
                uint32_t addr = sB + (uint32_t)(((kk * 16 + lr) * BPH + wn + 16 * jj + lc) * 2);
                LDSM_X4T(bf[jj][0], bf[jj][1], bf[jj][2], bf[jj][3], addr);
            }
            #pragma unroll
            for (int i = 0; i < MT; i++) {
                #pragma unroll
                for (int jj = 0; jj < 2; jj++) {
                    mma_f16(acc[i][2 * jj + 0], af[i], &bf[jj][0]);
                    mma_f16(acc[i][2 * jj + 1], af[i], &bf[jj][2]);
                }
            }
        }
        __syncthreads();
    }

    const int er = lane >> 2, ec = (lane & 3) * 2;
    #pragma unroll
    for (int i = 0; i < MT; i++) {
        #pragma unroll
        for (int rr = 0; rr < 2; rr++) {
            const int row = wm + 16 * i + er + 8 * rr;
            float*  Cfrow = WF ? Cfb + (size_t)row * ldc : nullptr;
            __half* Chrow = WH ? Chb + (size_t)row * ldc : nullptr;
            const float* Rrow = (MODE == 2) ? Rb + (size_t)row * ldres : nullptr;
            float inv = 0.f;
            if (MODE == 4) inv = 1.0f / Rv[row];
            #pragma unroll
            for (int j = 0; j < NT; j++) {
                const int col = wn + 8 * j + ec;
                float v0 = acc[i][j][2 * rr + 0];
                float v1 = acc[i][j][2 * rr + 1];
                if (MODE == 2) {
                    v0 += bias[bn + col]     + Rrow[col];
                    v1 += bias[bn + col + 1] + Rrow[col + 1];
                }
                if (MODE == 3) {
                    v0 += bias[bn + col];
                    v1 += bias[bn + col + 1];
                    v0 = 0.5f * v0 * (1.0f + erff(v0 * 0.70710678118654752f));
                    v1 = 0.5f * v1 * (1.0f + erff(v1 * 0.70710678118654752f));
                }
                if (MODE == 4) {
                    v0 = __expf(v0 * scale) * inv;
                    v1 = __expf(v1 * scale) * inv;
                }
                if (WF) *(float2*)&Cfrow[col] = make_float2(v0, v1);
                if (WH) *(uint32_t*)&Chrow[col] = packh2(v0, v1);
            }
        }
    }
}

// ---------------------------------------------------------------------------
// Fused attention pass 1 (flash-style): per CTA = (128 q rows, one b*h).
// Streams 16 KV chunks of 128: S = Q@K^T, P = exp(S/8) (regs, fp16 pack),
// rowsum += row sums, ctx += P@V. Writes y16 = ctx/rowsum and rowsum.
// 8 warps, each owns a 16-row block; Q fragments loaded once.
// ---------------------------------------------------------------------------
__global__ __launch_bounds__(256) void flash_fwd_kernel(
    const __half* __restrict__ qh, const __half* __restrict__ kT,
    const __half* __restrict__ kv, __half* __restrict__ y,
    float* __restrict__ rowsum)
{
    constexpr int QPH = 72;     // Q smem pitch (halves): 144 B
    constexpr int KPH = 136;    // K smem pitch: 272 B
    constexpr int VPH = 72;     // V smem pitch: 144 B
    constexpr int QBUF = 128 * QPH * 2;          // 18432
    constexpr int KBUF = 64 * KPH * 2;           // 17408
    constexpr int VBUF = 128 * VPH * 2;          // 18432

    extern __shared__ __align__(16) char smem[];
    const uint32_t sQ  = smem_u32(smem);
    const uint32_t sK0 = sQ + QBUF;
    const uint32_t sV0 = sK0 + 2 * KBUF;

    const int tid = threadIdx.x, wid = tid >> 5, lane = tid & 31;
    const int wm = wid * 16;
    const int qb = blockIdx.x, z = blockIdx.y;
    const int zb = z >> 4, zh = z & 15;

    const __half* Qg = qh + (size_t)zb * NQ * CC + zh * DH + (size_t)(qb * 128) * CC;
    const __half* Kg = kT + (size_t)zb * CC * NKV + (size_t)zh * DH * NKV;
    const __half* Vg = kv + (size_t)zb * NKV * 2 * CC + CC + zh * DH;

    // Q tile load: 128 rows x 64 halves
    #pragma unroll
    for (int u = 0; u < 4; u++) {
        int c = tid + u * 256;
        int row = c >> 3, col = c & 7;
        cpasync16(sQ + row * (QPH * 2) + col * 16, Qg + (size_t)row * CC + col * 8);
    }
    CP_COMMIT();

    auto issueKV = [&](int c) {
        const uint32_t dK = sK0 + (c & 1) * KBUF;
        const uint32_t dV = sV0 + (c & 1) * VBUF;
        #pragma unroll
        for (int u = 0; u < 4; u++) {
            int idx = tid + u * 256;
            int row = idx >> 4, col = idx & 15;
            cpasync16(dK + row * (KPH * 2) + col * 16,
                      Kg + (size_t)row * NKV + c * 128 + col * 8);
        }
        #pragma unroll
        for (int u = 0; u < 4; u++) {
            int idx = tid + u * 256;
            int row = idx >> 3, col = idx & 7;
            cpasync16(dV + row * (VPH * 2) + col * 16,
                      Vg + (size_t)(c * 128 + row) * (2 * CC) + col * 8);
        }
        CP_COMMIT();
    };
    issueKV(0);

    const int lr = ((lane >> 3) & 1) * 8 + (lane & 7);
    const int lc = ((lane >> 4) & 1) * 8;

    // Wait for Q + chunk0; load Q fragments once (af[kst][4], kst = k16 step)
    CP_WAIT(1);
    __syncthreads();
    uint32_t af[4][4];
    #pragma unroll
    for (int kst = 0; kst < 4; kst++) {
        uint32_t addr = sQ + (uint32_t)(((wm + lr) * QPH + kst * 16 + lc) * 2);
        LDSM_X4(af[kst][0], af[kst][1], af[kst][2], af[kst][3], addr);
    }

    float cacc[8][4];
    #pragma unroll
    for (int j = 0; j < 8; j++)
        #pragma unroll
        for (int v = 0; v < 4; v++) cacc[j][v] = 0.f;
    float rp0 = 0.f, rp1 = 0.f;

    for (int c = 0; c < 16; c++) {
        if (c + 1 < 16) { issueKV(c + 1); CP_WAIT(1); } else { CP_WAIT(0); }
        __syncthreads();
        const uint32_t sK = sK0 + (c & 1) * KBUF;
        const uint32_t sV = sV0 + (c & 1) * VBUF;

        // S = Q @ K^T : 16 x 128 per warp
        float sacc[16][4];
        #pragma unroll
        for (int t = 0; t < 16; t++)
            #pragma unroll
            for (int v = 0; v < 4; v++) sacc[t][v] = 0.f;

        #pragma unroll
        for (int jj = 0; jj < 8; jj++) {
            #pragma unroll
            for (int kst = 0; kst < 4; kst++) {
                uint32_t bf[4];
                uint32_t addr = sK + (uint32_t)(((kst * 16 + lr) * KPH + jj * 16 + lc) * 2);
                LDSM_X4T(bf[0], bf[1], bf[2], bf[3], addr);
                mma_f16(sacc[2 * jj + 0], af[kst], &bf[0]);
                mma_f16(sacc[2 * jj + 1], af[kst], &bf[2]);
            }
        }

        // P = exp(S/8): accumulate rowsum + pack A-fragments (pf[jj] = k16 block jj)
        uint32_t pf[8][4];
        #pragma unroll
        for (int jj = 0; jj < 8; jj++) {
            float e00 = __expf(sacc[2 * jj + 0][0] * 0.125f);
            float e01 = __expf(sacc[2 * jj + 0][1] * 0.125f);
            float e02 = __expf(sacc[2 * jj + 0][2] * 0.125f);
            float e03 = __expf(sacc[2 * jj + 0][3] * 0.125f);
            float e10 = __expf(sacc[2 * jj + 1][0] * 0.125f);
            float e11 = __expf(sacc[2 * jj + 1][1] * 0.125f);
            float e12 = __expf(sacc[2 * jj + 1][2] * 0.125f);
            float e13 = __expf(sacc[2 * jj + 1][3] * 0.125f);
            rp0 += e00 + e01 + e10 + e11;
            rp1 += e02 + e03 + e12 + e13;
            pf[jj][0] = packh2(e00, e01);
            pf[jj][1] = packh2(e02, e03);
            pf[jj][2] = packh2(e10, e11);
            pf[jj][3] = packh2(e12, e13);
        }

        // ctx += P @ V : 16 x 64 per warp
        #pragma unroll
        for (int jj = 0; jj < 8; jj++) {
            #pragma unroll
            for (int vv = 0; vv < 4; vv++) {
                uint32_t bv[4];
                uint32_t addr = sV + (uint32_t)(((jj * 16 + lr) * VPH + vv * 16 + lc) * 2);
                LDSM_X4T(bv[0], bv[1], bv[2], bv[3], addr);
                mma_f16(cacc[2 * vv + 0], pf[jj], &bv[0]);
                mma_f16(cacc[2 * vv + 1], pf[jj], &bv[2]);
            }
        }
        __syncthreads();
    }

    // reduce rowsum across the quad (lane%4 holds different columns)
    rp0 += __shfl_xor_sync(~0u, rp0, 1); rp0 += __shfl_xor_sync(~0u, rp0, 2);
    rp1 += __shfl_xor_sync(~0u, rp1, 1); rp1 += __shfl_xor_sync(~0u, rp1, 2);
    const int er = lane >> 2, ec = (lane & 3) * 2;
    const float inv0 = 1.0f / rp0, inv1 = 1.0f / rp1;

    __half* Yb = y + (size_t)zb * NQ * CC + (size_t)(qb * 128) * CC + zh * DH;
    __half* Yr0 = Yb + (size_t)(wm + er) * CC;
    __half* Yr1 = Yb + (size_t)(wm + er + 8) * CC;
    #pragma unroll
    for (int j = 0; j < 8; j++) {
        int col = 8 * j + ec;
        *(uint32_t*)&Yr0[col] = packh2(cacc[j][0] * inv0, cacc[j][1] * inv0);
        *(uint32_t*)&Yr1[col] = packh2(cacc[j][2] * inv1, cacc[j][3] * inv1);
    }
    if ((lane & 3) == 0) {
        rowsum[(size_t)z * NQ + qb * 128 + wm + er]     = rp0;
        rowsum[(size_t)z * NQ + qb * 128 + wm + er + 8] = rp1;
    }
}

// ---------------------------------------------------------------------------
__global__ void f2h_kernel(const float* __restrict__ in, __half* __restrict__ out, int n)
{
    int i = (blockIdx.x * blockDim.x + threadIdx.x) * 4;
    if (i < n) {
        float4 v = *(const float4*)(in + i);
        uint2 u = { packh2(v.x, v.y), packh2(v.z, v.w) };
        *(uint2*)(out + i) = u;
    }
}

// ---------------------------------------------------------------------------
__global__ void transpose_h(const __half* __restrict__ in, int ld_in, long sb_in,
                            __half* __restrict__ out, int ld_out, long sb_out)
{
    __shared__ __half tile[32][34];
    const __half* ip = in + (long)blockIdx.z * sb_in;
    __half* op = out + (long)blockIdx.z * sb_out;
    int r0 = blockIdx.y * 32, c0 = blockIdx.x * 32;
    int x = threadIdx.x, y = threadIdx.y;
    #pragma unroll
    for (int j = 0; j < 32; j += 8)
        tile[y + j][x] = ip[(size_t)(r0 + y + j) * ld_in + c0 + x];
    __syncthreads();
    #pragma unroll
    for (int j = 0; j < 32; j += 8)
        op[(size_t)(c0 + y + j) * ld_out + r0 + x] = tile[x][y + j];
}

// ---------------------------------------------------------------------------
__global__ void ln_kernel_h(const float* __restrict__ x, const float* __restrict__ g,
                            const float* __restrict__ be, __half* __restrict__ out, int ccols)
{
    int row = blockIdx.x;
    const float* p = x + (size_t)row * ccols;
    __half* o = out + (size_t)row * ccols;
    int t = threadIdx.x;

    float s = 0.f, s2 = 0.f;
    for (int i = t; i < ccols; i += blockDim.x) { float v = p[i]; s += v; s2 += v * v; }
    __shared__ float r1[8], r2[8];
    #pragma unroll
    for (int off = 16; off; off >>= 1) {
        s  += __shfl_xor_sync(~0u, s,  off);
        s2 += __shfl_xor_sync(~0u, s2, off);
    }
    if ((t & 31) == 0) { r1[t >> 5] = s; r2[t >> 5] = s2; }
    __syncthreads();
    float ts = 0.f, ts2 = 0.f;
    #pragma unroll
    for (int i = 0; i < 8; i++) { ts += r1[i]; ts2 += r2[i]; }
    float mean = ts / ccols;
    float var  = ts2 / ccols - mean * mean;
    float inv  = rsqrtf(var + 1e-5f);
    for (int i = t; i < ccols; i += blockDim.x)
        o[i] = __float2half((p[i] - mean) * inv * g[i] + be[i]);
}

// ---------------------------------------------------------------------------
extern "C" void kernel_launch(void* const* d_in, const int* in_sizes, int n_in,
                              void* d_out, int out_size)
{
    const float* q     = (const float*)d_in[0];
    const float* x     = (const float*)d_in[1];
    const float* Wq    = (const float*)d_in[2];
    const float* Wkv   = (const float*)d_in[3];
    const float* Wproj = (const float*)d_in[4];
    const float* bproj = (const float*)d_in[5];
    const float* W1    = (const float*)d_in[6];
    const float* b1    = (const float*)d_in[7];
    const float* W2    = (const float*)d_in[8];
    const float* b2    = (const float*)d_in[9];
    const float* g1    = (const float*)d_in[10];
    const float* be1   = (const float*)d_in[11];
    const float* g2    = (const float*)d_in[12];
    const float* be2   = (const float*)d_in[13];

    float* out_q    = (float*)d_out;
    float* out_attn = out_q + (size_t)BB * NQ * CC;

    __half *q16, *xn16, *qh16, *kv16, *kT16, *y16, *t16, *hid16;
    __half *wq16, *wkv16, *wp16, *w116, *w216;
    float  *q2, *rowsum;
    cudaGetSymbolAddress((void**)&q16,  g_q16);
    cudaGetSymbolAddress((void**)&xn16, g_xn16);
    cudaGetSymbolAddress((void**)&qh16, g_qh16);
    cudaGetSymbolAddress((void**)&kv16, g_kv16);
    cudaGetSymbolAddress((void**)&kT16, g_kT16);
    cudaGetSymbolAddress((void**)&y16,  g_y16);
    cudaGetSymbolAddress((void**)&t16,  g_t16);
    cudaGetSymbolAddress((void**)&hid16,g_hid16);
    cudaGetSymbolAddress((void**)&q2,   g_q2);
    cudaGetSymbolAddress((void**)&rowsum, g_rowsum);
    cudaGetSymbolAddress((void**)&wq16, g_wq16);
    cudaGetSymbolAddress((void**)&wkv16,g_wkv16);
    cudaGetSymbolAddress((void**)&wp16, g_wp16);
    cudaGetSymbolAddress((void**)&w116, g_w116);
    cudaGetSymbolAddress((void**)&w216, g_w216);

    const int SM128 = 3 * (128 * 40 * 2 + 32 * 136 * 2);                 // 56832
    const int SMF   = 128 * 72 * 2 + 2 * (64 * 136 * 2) + 2 * (128 * 72 * 2);  // 90112
    cudaFuncSetAttribute((const void*)mma_gemm_h<128, 0, false, true>,  cudaFuncAttributeMaxDynamicSharedMemorySize, SM128);
    cudaFuncSetAttribute((const void*)mma_gemm_h<128, 2, true,  false>, cudaFuncAttributeMaxDynamicSharedMemorySize, SM128);
    cudaFuncSetAttribute((const void*)mma_gemm_h<128, 3, false, true>,  cudaFuncAttributeMaxDynamicSharedMemorySize, SM128);
    cudaFuncSetAttribute((const void*)mma_gemm_h<128, 4, true,  false>, cudaFuncAttributeMaxDynamicSharedMemorySize, SM128);
    cudaFuncSetAttribute((const void*)flash_fwd_kernel, cudaFuncAttributeMaxDynamicSharedMemorySize, SMF);

    dim3 tb(32, 8);

    // 0) fp16 conversions (weights + q)
    f2h_kernel<<<(BB * NQ * CC) / 1024, 256>>>(q,  q16,  BB * NQ * CC);
    f2h_kernel<<<(CC * CC) / 1024, 256>>>(Wq,    wq16,  CC * CC);
    f2h_kernel<<<(CC * 2 * CC) / 1024, 256>>>(Wkv, wkv16, CC * 2 * CC);
    f2h_kernel<<<(CC * CC) / 1024, 256>>>(Wproj, wp16,  CC * CC);
    f2h_kernel<<<(CC * HID) / 1024, 256>>>(W1,   w116,  CC * HID);
    f2h_kernel<<<(HID * CC) / 1024, 256>>>(W2,   w216,  HID * CC);

    // 1) xn16 = LN(x)
    ln_kernel_h<<<BB * NKV, 256>>>(x, g1, be1, xn16, CC);

    // 2) qh16 = q16 @ Wq16
    mma_gemm_h<128, 0, false, true><<<dim3(CC / 128, BB * NQ / 128, 1), 256, SM128>>>(
        q16, CC, 0, 0, wq16, CC, 0, 0, nullptr, qh16, CC, 0, 0, CC, nullptr, nullptr, 0, 0.f);

    // 3) kv16 = xn16 @ Wkv16
    mma_gemm_h<128, 0, false, true><<<dim3(2 * CC / 128, BB * NKV / 128, 1), 256, SM128>>>(
        xn16, CC, 0, 0, wkv16, 2 * CC, 0, 0, nullptr, kv16, 2 * CC, 0, 0, CC, nullptr, nullptr, 0, 0.f);

    // 4) kT16 = transpose of k-half of kv16
    transpose_h<<<dim3(CC / 32, NKV / 32, BB), tb>>>(
        kv16, 2 * CC, (long)NKV * 2 * CC, kT16, NKV, (long)CC * NKV);

    // 5) fused attention: rowsum + y16 = softmax(S) @ V
    flash_fwd_kernel<<<dim3(NQ / 128, BB * NH), 256, SMF>>>(
        qh16, kT16, kv16, y16, rowsum);

    // 6) attn = exp(s/8)/rowsum -> fp32 out_attn (mandatory output)
    mma_gemm_h<128, 4, true, false><<<dim3(NKV / 128, NQ / 128, BB * NH), 256, SM128>>>(
        qh16, CC, (long)NQ * CC, DH,
        kT16, NKV, (long)CC * NKV, (long)DH * NKV,
        out_attn, nullptr, NKV, (long)NH * NQ * NKV, (long)NQ * NKV,
        DH, nullptr, rowsum, 0, 0.125f);

    // 7) q2 = q + y16 @ Wp16 + bproj   (fp32)
    mma_gemm_h<128, 2, true, false><<<dim3(CC / 128, BB * NQ / 128, 1), 256, SM128>>>(
        y16, CC, 0, 0, wp16, CC, 0, 0, q2, nullptr, CC, 0, 0, CC, bproj, q, CC, 0.f);

    // 8) t16 = LN(q2)
    ln_kernel_h<<<BB * NQ, 256>>>(q2, g2, be2, t16, CC);

    // 9) hid16 = gelu(t16 @ W116 + b1)
    mma_gemm_h<128, 3, false, true><<<dim3(HID / 128, BB * NQ / 128, 1), 256, SM128>>>(
        t16, CC, 0, 0, w116, HID, 0, 0, nullptr, hid16, HID, 0, 0, CC, b1, nullptr, 0, 0.f);

    // 10) out_q = q2 + hid16 @ W216 + b2   (fp32)
    mma_gemm_h<128, 2, true, false><<<dim3(CC / 128, BB * NQ / 128, 1), 256, SM128>>>(
        hid16, HID, 0, 0, w216, CC, 0, 0, out_q, nullptr, CC, 0, 0, HID, b2, q2, CC, 0.f);
}